// round 4
// baseline (speedup 1.0000x reference)
#include <cuda_runtime.h>
#include <cuda_bf16.h>
#include <cstdint>
#include <math.h>

// Problem: x[4,2048,1024], W_qkv[3072,1024], W_proj[1024,1024] -> out[4,2048,1024]
#define KDIM 1024

// ---------------- device scratch (allocation-free) ----------------
__device__ float g_Q[8388608];
__device__ float g_K[8388608];
__device__ float g_V[8388608];
__device__ __nv_bfloat16 g_Xhi[8388608];
__device__ __nv_bfloat16 g_Xlo[8388608];
__device__ __nv_bfloat16 g_Wqh[3145728];
__device__ __nv_bfloat16 g_Wql[3145728];
__device__ __nv_bfloat16 g_Wph[1048576];
__device__ __nv_bfloat16 g_Wpl[1048576];
__device__ __nv_bfloat16 g_Yhi[8388608];
__device__ __nv_bfloat16 g_Ylo[8388608];

__device__ __forceinline__ uint32_t smem_u32(const void* p) {
    uint32_t a;
    asm("{ .reg .u64 t; cvta.to.shared.u64 t, %1; cvt.u32.u64 %0, t; }" : "=r"(a) : "l"(p));
    return a;
}

#define LDSM_X4(r0, r1, r2, r3, addr) \
    asm volatile("ldmatrix.sync.aligned.m8n8.x4.shared.b16 {%0,%1,%2,%3}, [%4];" \
                 : "=r"(r0), "=r"(r1), "=r"(r2), "=r"(r3) : "r"(addr))

#define MMA16816(c, a, b) \
    asm volatile("mma.sync.aligned.m16n8k16.row.col.f32.bf16.bf16.f32 " \
                 "{%0,%1,%2,%3}, {%4,%5,%6,%7}, {%8,%9}, {%0,%1,%2,%3};" \
                 : "+f"((c)[0]), "+f"((c)[1]), "+f"((c)[2]), "+f"((c)[3]) \
                 : "r"((a)[0]), "r"((a)[1]), "r"((a)[2]), "r"((a)[3]), \
                   "r"((b)[0]), "r"((b)[1]))

// ---------------------------------------------------------------------------
// split kernel: fp32 -> (bf16 hi, bf16 lo), lo = bf16(x - float(hi))
// ---------------------------------------------------------------------------
__global__ __launch_bounds__(256) void split_kernel(const float* __restrict__ src,
                                                    __nv_bfloat16* __restrict__ hi,
                                                    __nv_bfloat16* __restrict__ lo,
                                                    int n4)
{
    int i = blockIdx.x * blockDim.x + threadIdx.x;
    if (i >= n4) return;
    float4 v = ((const float4*)src)[i];
    float a[4] = {v.x, v.y, v.z, v.w};
    __nv_bfloat16 h[4], l[4];
#pragma unroll
    for (int j = 0; j < 4; ++j) {
        h[j] = __float2bfloat16(a[j]);
        l[j] = __float2bfloat16(a[j] - __bfloat162float(h[j]));
    }
    __nv_bfloat162* hp = (__nv_bfloat162*)hi;
    __nv_bfloat162* lp = (__nv_bfloat162*)lo;
    hp[2 * i + 0] = __nv_bfloat162{h[0], h[1]};
    hp[2 * i + 1] = __nv_bfloat162{h[2], h[3]};
    lp[2 * i + 0] = __nv_bfloat162{l[0], l[1]};
    lp[2 * i + 1] = __nv_bfloat162{l[2], l[3]};
}

// ---------------------------------------------------------------------------
// HMMA split-bf16 GEMM: C[M,N] = A[M,K] * B[N,K]^T  (3 passes: hh, lh, hl)
// CTA 128x128, 256 thr = 8 warps (2M x 4N), warp 64x32 = 4x4 m16n8k16 tiles.
// K staged 64/iter; smem row stride 72 bf16 (144B) -> ldmatrix conflict-free.
// mode 0: scatter into g_Q/g_K/g_V [B,H,T,Dh]; mode 1: row-major fp32 out.
// ---------------------------------------------------------------------------
#define GSTRIDE 72
#define GTILE (128 * GSTRIDE * 2)        // 18432 B per tile
#define GSM_TOTAL (4 * GTILE)            // 73728 B

__global__ __launch_bounds__(256)
void gemm_hmma_kernel(const __nv_bfloat16* __restrict__ Ahi,
                      const __nv_bfloat16* __restrict__ Alo,
                      const __nv_bfloat16* __restrict__ Bhi,
                      const __nv_bfloat16* __restrict__ Blo,
                      float* __restrict__ Out, int mode)
{
    extern __shared__ char smem[];
    char* sAhi = smem;
    char* sAlo = smem + GTILE;
    char* sBhi = smem + 2 * GTILE;
    char* sBlo = smem + 3 * GTILE;

    const int tid = threadIdx.x;
    const int wid = tid >> 5;
    const int l = tid & 31;
    const int m0 = blockIdx.y << 7;
    const int n0 = blockIdx.x << 7;
    const int warpM = wid >> 2;          // 0..1
    const int warpN = wid & 3;           // 0..3

    float acc[4][4][4];
#pragma unroll
    for (int i = 0; i < 4; ++i)
#pragma unroll
        for (int j = 0; j < 4; ++j)
#pragma unroll
            for (int k = 0; k < 4; ++k) acc[i][j][k] = 0.f;

    // ldmatrix lane address bases (bf16-element offsets *2 = bytes)
    const int aRow = warpM * 64 + (l & 15);
    const int aCol = (l >> 4) << 3;
    const uint32_t aOff = (uint32_t)(aRow * GSTRIDE + aCol) * 2;
    const int bRow = warpN * 32 + (l & 7) + ((l >> 4) << 3);
    const int bCol = ((l >> 3) & 1) << 3;
    const uint32_t bOff = (uint32_t)(bRow * GSTRIDE + bCol) * 2;

    const uint32_t sAhi_u = smem_u32(sAhi) + aOff;
    const uint32_t sAlo_u = smem_u32(sAlo) + aOff;
    const uint32_t sBhi_u = smem_u32(sBhi) + bOff;
    const uint32_t sBlo_u = smem_u32(sBlo) + bOff;

    for (int iter = 0; iter < KDIM / 64; ++iter) {
        const int k0 = iter << 6;
        // load 4 tiles: 128 rows x 64 bf16 = 8 x 16B per row
#pragma unroll
        for (int t = 0; t < 4; ++t) {
            int idx = tid + (t << 8);           // 0..1023
            int row = idx >> 3;
            int q = idx & 7;
            size_t ga = (size_t)(m0 + row) * KDIM + k0 + (q << 3);
            size_t gb = (size_t)(n0 + row) * KDIM + k0 + (q << 3);
            int so = row * GSTRIDE * 2 + (q << 4);
            *(uint4*)(sAhi + so) = *(const uint4*)(Ahi + ga);
            *(uint4*)(sAlo + so) = *(const uint4*)(Alo + ga);
            *(uint4*)(sBhi + so) = *(const uint4*)(Bhi + gb);
            *(uint4*)(sBlo + so) = *(const uint4*)(Blo + gb);
        }
        __syncthreads();

#pragma unroll
        for (int ks = 0; ks < 4; ++ks) {
            const uint32_t kb = (uint32_t)(ks << 5);   // ks*16 bf16 = 32 B
            uint32_t bh[4][2], bl[4][2];
#pragma unroll
            for (int np = 0; np < 2; ++np) {
                uint32_t o = kb + (uint32_t)(np * 16 * GSTRIDE * 2);
                LDSM_X4(bh[2 * np][0], bh[2 * np][1], bh[2 * np + 1][0], bh[2 * np + 1][1], sBhi_u + o);
                LDSM_X4(bl[2 * np][0], bl[2 * np][1], bl[2 * np + 1][0], bl[2 * np + 1][1], sBlo_u + o);
            }
            uint32_t ah[4][4], al[4][4];
#pragma unroll
            for (int mt = 0; mt < 4; ++mt) {
                uint32_t o = kb + (uint32_t)(mt * 16 * GSTRIDE * 2);
                LDSM_X4(ah[mt][0], ah[mt][1], ah[mt][2], ah[mt][3], sAhi_u + o);
                LDSM_X4(al[mt][0], al[mt][1], al[mt][2], al[mt][3], sAlo_u + o);
            }
#pragma unroll
            for (int mt = 0; mt < 4; ++mt)
#pragma unroll
                for (int nt = 0; nt < 4; ++nt) {
                    MMA16816(acc[mt][nt], ah[mt], bh[nt]);
                    MMA16816(acc[mt][nt], al[mt], bh[nt]);
                    MMA16816(acc[mt][nt], ah[mt], bl[nt]);
                }
        }
        __syncthreads();
    }

    // epilogue: lane holds (row g, col t*2..+1) and (row g+8, ...)
#pragma unroll
    for (int mt = 0; mt < 4; ++mt) {
#pragma unroll
        for (int nt = 0; nt < 4; ++nt) {
            int r0 = m0 + warpM * 64 + mt * 16 + (l >> 2);
            int col = n0 + warpN * 32 + nt * 8 + ((l & 3) << 1);
#pragma unroll
            for (int half = 0; half < 2; ++half) {
                int m = r0 + half * 8;
                float2 v = make_float2(acc[mt][nt][half * 2], acc[mt][nt][half * 2 + 1]);
                if (mode == 0) {
                    int which = col >> 10;
                    int c = col & 1023;
                    int h = c >> 6;
                    int d = c & 63;
                    int bb = m >> 11;
                    int t = m & 2047;
                    float* base = (which == 0) ? g_Q : (which == 1) ? g_K : g_V;
                    *(float2*)&base[(size_t)(((bb << 4) | h) * 2048 + t) * 64 + d] = v;
                } else {
                    *(float2*)&Out[(size_t)m * 1024 + col] = v;
                }
            }
        }
    }
}

// ---------------------------------------------------------------------------
// Flash attention, fp32 (unchanged). Epilogue writes split-bf16 Y.
// ---------------------------------------------------------------------------
__global__ __launch_bounds__(256) void flash_kernel()
{
    extern __shared__ float sm[];
    float* Qs = sm;             // [d][r]  64x64
    float* Ks = sm + 4096;      // [d][c]  64x64
    float* Vs = sm + 8192;      // [j][d]  64x64
    float* Ps = sm + 12288;     // [r][j]  64x68

    const int tid = threadIdx.x;
    const int tx = tid & 15;
    const int ty = tid >> 4;
    const int bh = blockIdx.y;
    const int q0 = blockIdx.x << 6;

    const float* Qb = g_Q + (size_t)bh * 2048 * 64;
    const float* Kb = g_K + (size_t)bh * 2048 * 64;
    const float* Vb = g_V + (size_t)bh * 2048 * 64;

#pragma unroll
    for (int it = 0; it < 4; ++it) {
        int idx = tid + (it << 8);
        int r = idx >> 4;
        int d4 = (idx & 15) << 2;
        float4 v = *(const float4*)&Qb[(size_t)(q0 + r) * 64 + d4];
        Qs[(d4 + 0) * 64 + r] = v.x;
        Qs[(d4 + 1) * 64 + r] = v.y;
        Qs[(d4 + 2) * 64 + r] = v.z;
        Qs[(d4 + 3) * 64 + r] = v.w;
    }

    float m_i[4], l_i[4], acc[4][4];
#pragma unroll
    for (int i = 0; i < 4; ++i) {
        m_i[i] = -INFINITY;
        l_i[i] = 0.f;
#pragma unroll
        for (int j = 0; j < 4; ++j) acc[i][j] = 0.f;
    }

    for (int jb = 0; jb < 32; ++jb) {
        __syncthreads();
        int k0 = jb << 6;
#pragma unroll
        for (int it = 0; it < 4; ++it) {
            int idx = tid + (it << 8);
            int c = idx >> 4;
            int d4 = (idx & 15) << 2;
            float4 v = *(const float4*)&Kb[(size_t)(k0 + c) * 64 + d4];
            Ks[(d4 + 0) * 64 + c] = v.x;
            Ks[(d4 + 1) * 64 + c] = v.y;
            Ks[(d4 + 2) * 64 + c] = v.z;
            Ks[(d4 + 3) * 64 + c] = v.w;
            float4 w = *(const float4*)&Vb[(size_t)(k0 + c) * 64 + d4];
            *(float4*)&Vs[c * 64 + d4] = w;
        }
        __syncthreads();

        float s[4][4];
#pragma unroll
        for (int i = 0; i < 4; ++i)
#pragma unroll
            for (int j = 0; j < 4; ++j) s[i][j] = 0.f;

#pragma unroll 16
        for (int d = 0; d < 64; ++d) {
            float4 qv = *(const float4*)&Qs[d * 64 + (ty << 2)];
            float4 kv = *(const float4*)&Ks[d * 64 + (tx << 2)];
            float qa[4] = {qv.x, qv.y, qv.z, qv.w};
            float ka[4] = {kv.x, kv.y, kv.z, kv.w};
#pragma unroll
            for (int i = 0; i < 4; ++i)
#pragma unroll
                for (int j = 0; j < 4; ++j)
                    s[i][j] = fmaf(qa[i], ka[j], s[i][j]);
        }

#pragma unroll
        for (int i = 0; i < 4; ++i) {
#pragma unroll
            for (int j = 0; j < 4; ++j) s[i][j] *= 0.125f;

            float mloc = fmaxf(fmaxf(s[i][0], s[i][1]), fmaxf(s[i][2], s[i][3]));
#pragma unroll
            for (int off = 8; off; off >>= 1)
                mloc = fmaxf(mloc, __shfl_xor_sync(0xffffffffu, mloc, off));

            float mnew = fmaxf(m_i[i], mloc);
            float alpha = __expf(m_i[i] - mnew);
            m_i[i] = mnew;

            float p0 = __expf(s[i][0] - mnew);
            float p1 = __expf(s[i][1] - mnew);
            float p2 = __expf(s[i][2] - mnew);
            float p3 = __expf(s[i][3] - mnew);
            float lloc = (p0 + p1) + (p2 + p3);
#pragma unroll
            for (int off = 8; off; off >>= 1)
                lloc += __shfl_xor_sync(0xffffffffu, lloc, off);
            l_i[i] = l_i[i] * alpha + lloc;

#pragma unroll
            for (int j = 0; j < 4; ++j) acc[i][j] *= alpha;

            *(float4*)&Ps[((ty << 2) + i) * 68 + (tx << 2)] = make_float4(p0, p1, p2, p3);
        }
        __syncthreads();

#pragma unroll 4
        for (int j4 = 0; j4 < 64; j4 += 4) {
            float pr[4][4];
#pragma unroll
            for (int i = 0; i < 4; ++i) {
                float4 p4 = *(const float4*)&Ps[((ty << 2) + i) * 68 + j4];
                pr[i][0] = p4.x; pr[i][1] = p4.y; pr[i][2] = p4.z; pr[i][3] = p4.w;
            }
#pragma unroll
            for (int jj = 0; jj < 4; ++jj) {
                float4 vv = *(const float4*)&Vs[(j4 + jj) * 64 + (tx << 2)];
#pragma unroll
                for (int i = 0; i < 4; ++i) {
                    acc[i][0] = fmaf(pr[i][jj], vv.x, acc[i][0]);
                    acc[i][1] = fmaf(pr[i][jj], vv.y, acc[i][1]);
                    acc[i][2] = fmaf(pr[i][jj], vv.z, acc[i][2]);
                    acc[i][3] = fmaf(pr[i][jj], vv.w, acc[i][3]);
                }
            }
        }
    }

    int bb = bh >> 4;
    int h = bh & 15;
#pragma unroll
    for (int i = 0; i < 4; ++i) {
        float inv = 1.f / l_i[i];
        int t = q0 + (ty << 2) + i;
        size_t base = (size_t)(bb * 2048 + t) * 1024 + h * 64 + (tx << 2);
        float v[4] = {acc[i][0] * inv, acc[i][1] * inv, acc[i][2] * inv, acc[i][3] * inv};
        __nv_bfloat16 hh[4], ll[4];
#pragma unroll
        for (int j = 0; j < 4; ++j) {
            hh[j] = __float2bfloat16(v[j]);
            ll[j] = __float2bfloat16(v[j] - __bfloat162float(hh[j]));
        }
        *(__nv_bfloat162*)&g_Yhi[base]     = __nv_bfloat162{hh[0], hh[1]};
        *(__nv_bfloat162*)&g_Yhi[base + 2] = __nv_bfloat162{hh[2], hh[3]};
        *(__nv_bfloat162*)&g_Ylo[base]     = __nv_bfloat162{ll[0], ll[1]};
        *(__nv_bfloat162*)&g_Ylo[base + 2] = __nv_bfloat162{ll[2], ll[3]};
    }
}

// ---------------------------------------------------------------------------
extern "C" void kernel_launch(void* const* d_in, const int* in_sizes, int n_in,
                              void* d_out, int out_size)
{
    (void)in_sizes; (void)n_in; (void)out_size;
    const float* x = (const float*)d_in[0];
    const float* wq = (const float*)d_in[1];
    const float* wp = (const float*)d_in[2];
    float* out = (float*)d_out;

    const int flash_smem = (12288 + 64 * 68) * 4;
    cudaFuncSetAttribute(flash_kernel, cudaFuncAttributeMaxDynamicSharedMemorySize, flash_smem);
    cudaFuncSetAttribute(gemm_hmma_kernel, cudaFuncAttributeMaxDynamicSharedMemorySize, GSM_TOTAL);

    __nv_bfloat16 *xhi, *xlo, *wqh, *wql, *wph, *wpl, *yhi, *ylo;
    cudaGetSymbolAddress((void**)&xhi, g_Xhi);
    cudaGetSymbolAddress((void**)&xlo, g_Xlo);
    cudaGetSymbolAddress((void**)&wqh, g_Wqh);
    cudaGetSymbolAddress((void**)&wql, g_Wql);
    cudaGetSymbolAddress((void**)&wph, g_Wph);
    cudaGetSymbolAddress((void**)&wpl, g_Wpl);
    cudaGetSymbolAddress((void**)&yhi, g_Yhi);
    cudaGetSymbolAddress((void**)&ylo, g_Ylo);

    split_kernel<<<8192, 256>>>(x, xhi, xlo, 2097152);
    split_kernel<<<3072, 256>>>(wq, wqh, wql, 786432);
    split_kernel<<<1024, 256>>>(wp, wph, wpl, 262144);

    gemm_hmma_kernel<<<dim3(24, 64), 256, GSM_TOTAL>>>(xhi, xlo, wqh, wql, nullptr, 0);
    flash_kernel<<<dim3(32, 64), 256, flash_smem>>>();
    gemm_hmma_kernel<<<dim3(8, 64), 256, GSM_TOTAL>>>(yhi, ylo, wph, wpl, out, 1);
}

// round 5
// speedup vs baseline: 3.8274x; 3.8274x over previous
#include <cuda_runtime.h>
#include <cuda_bf16.h>
#include <cstdint>
#include <math.h>

// Problem: x[4,2048,1024], W_qkv[3072,1024], W_proj[1024,1024] -> out[4,2048,1024]
#define KDIM 1024

// ---------------- device scratch (allocation-free) ----------------
__device__ __nv_bfloat16 g_Xhi[8388608];
__device__ __nv_bfloat16 g_Xlo[8388608];
__device__ __nv_bfloat16 g_Wqh[3145728];
__device__ __nv_bfloat16 g_Wql[3145728];
__device__ __nv_bfloat16 g_Wph[1048576];
__device__ __nv_bfloat16 g_Wpl[1048576];
__device__ __nv_bfloat16 g_Qh[8388608];
__device__ __nv_bfloat16 g_Ql[8388608];
__device__ __nv_bfloat16 g_Kh[8388608];
__device__ __nv_bfloat16 g_Kl[8388608];
__device__ __nv_bfloat16 g_Vh[8388608];
__device__ __nv_bfloat16 g_Vl[8388608];
__device__ __nv_bfloat16 g_Yhi[8388608];
__device__ __nv_bfloat16 g_Ylo[8388608];

__device__ __forceinline__ uint32_t smem_u32(const void* p) {
    uint32_t a;
    asm("{ .reg .u64 t; cvta.to.shared.u64 t, %1; cvt.u32.u64 %0, t; }" : "=r"(a) : "l"(p));
    return a;
}

#define LDSM_X4(r0, r1, r2, r3, addr) \
    asm volatile("ldmatrix.sync.aligned.m8n8.x4.shared.b16 {%0,%1,%2,%3}, [%4];" \
                 : "=r"(r0), "=r"(r1), "=r"(r2), "=r"(r3) : "r"(addr))

#define LDSM_X4_T(r0, r1, r2, r3, addr) \
    asm volatile("ldmatrix.sync.aligned.m8n8.x4.trans.shared.b16 {%0,%1,%2,%3}, [%4];" \
                 : "=r"(r0), "=r"(r1), "=r"(r2), "=r"(r3) : "r"(addr))

#define MMA16816(c, a, b) \
    asm volatile("mma.sync.aligned.m16n8k16.row.col.f32.bf16.bf16.f32 " \
                 "{%0,%1,%2,%3}, {%4,%5,%6,%7}, {%8,%9}, {%0,%1,%2,%3};" \
                 : "+f"((c)[0]), "+f"((c)[1]), "+f"((c)[2]), "+f"((c)[3]) \
                 : "r"((a)[0]), "r"((a)[1]), "r"((a)[2]), "r"((a)[3]), \
                   "r"((b)[0]), "r"((b)[1]))

// split pair (a,b) -> bf16x2 hi (truncated top-16-bits), bf16x2 lo (exact residual)
__device__ __forceinline__ void split2(float a, float b, uint32_t& hp, uint32_t& lp) {
    uint32_t ua = __float_as_uint(a), ub = __float_as_uint(b);
    hp = __byte_perm(ua, ub, 0x7632);
    float la = a - __uint_as_float(ua & 0xFFFF0000u);
    float lb = b - __uint_as_float(ub & 0xFFFF0000u);
    __nv_bfloat162 t = __float22bfloat162_rn(make_float2(la, lb));
    lp = *(uint32_t*)&t;
}

// ---------------------------------------------------------------------------
// split kernel: fp32 -> (bf16 hi, bf16 lo)
// ---------------------------------------------------------------------------
__global__ __launch_bounds__(256) void split_kernel(const float* __restrict__ src,
                                                    __nv_bfloat16* __restrict__ hi,
                                                    __nv_bfloat16* __restrict__ lo,
                                                    int n4)
{
    int i = blockIdx.x * blockDim.x + threadIdx.x;
    if (i >= n4) return;
    float4 v = ((const float4*)src)[i];
    uint32_t h0, l0, h1, l1;
    split2(v.x, v.y, h0, l0);
    split2(v.z, v.w, h1, l1);
    uint2* hp = (uint2*)hi;
    uint2* lp = (uint2*)lo;
    hp[i] = make_uint2(h0, h1);
    lp[i] = make_uint2(l0, l1);
}

// ---------------------------------------------------------------------------
// HMMA split-bf16 GEMM: C[M,N] = A[M,K] * B[N,K]^T  (3 passes: hh, lh, hl)
// CTA 128x128, 8 warps (2M x 4N), warp 64x32.
// mode 0: split-bf16 scatter into g_Qh/l, g_Kh/l, g_Vh/l [B,H,T,Dh]
// mode 1: row-major fp32 Out
// ---------------------------------------------------------------------------
#define GSTRIDE 72
#define GTILE (128 * GSTRIDE * 2)
#define GSM_TOTAL (4 * GTILE)

__global__ __launch_bounds__(256)
void gemm_hmma_kernel(const __nv_bfloat16* __restrict__ Ahi,
                      const __nv_bfloat16* __restrict__ Alo,
                      const __nv_bfloat16* __restrict__ Bhi,
                      const __nv_bfloat16* __restrict__ Blo,
                      float* __restrict__ Out, int mode)
{
    extern __shared__ char smem[];
    char* sAhi = smem;
    char* sAlo = smem + GTILE;
    char* sBhi = smem + 2 * GTILE;
    char* sBlo = smem + 3 * GTILE;

    const int tid = threadIdx.x;
    const int wid = tid >> 5;
    const int l = tid & 31;
    const int m0 = blockIdx.y << 7;
    const int n0 = blockIdx.x << 7;
    const int warpM = wid >> 2;
    const int warpN = wid & 3;

    float acc[4][4][4];
#pragma unroll
    for (int i = 0; i < 4; ++i)
#pragma unroll
        for (int j = 0; j < 4; ++j)
#pragma unroll
            for (int k = 0; k < 4; ++k) acc[i][j][k] = 0.f;

    const int aRow = warpM * 64 + (l & 15);
    const int aCol = (l >> 4) << 3;
    const uint32_t aOff = (uint32_t)(aRow * GSTRIDE + aCol) * 2;
    const int bRow = warpN * 32 + (l & 7) + ((l >> 4) << 3);
    const int bCol = ((l >> 3) & 1) << 3;
    const uint32_t bOff = (uint32_t)(bRow * GSTRIDE + bCol) * 2;

    const uint32_t sAhi_u = smem_u32(sAhi) + aOff;
    const uint32_t sAlo_u = smem_u32(sAlo) + aOff;
    const uint32_t sBhi_u = smem_u32(sBhi) + bOff;
    const uint32_t sBlo_u = smem_u32(sBlo) + bOff;

    for (int iter = 0; iter < KDIM / 64; ++iter) {
        const int k0 = iter << 6;
#pragma unroll
        for (int t = 0; t < 4; ++t) {
            int idx = tid + (t << 8);
            int row = idx >> 3;
            int q = idx & 7;
            size_t ga = (size_t)(m0 + row) * KDIM + k0 + (q << 3);
            size_t gb = (size_t)(n0 + row) * KDIM + k0 + (q << 3);
            int so = row * GSTRIDE * 2 + (q << 4);
            *(uint4*)(sAhi + so) = *(const uint4*)(Ahi + ga);
            *(uint4*)(sAlo + so) = *(const uint4*)(Alo + ga);
            *(uint4*)(sBhi + so) = *(const uint4*)(Bhi + gb);
            *(uint4*)(sBlo + so) = *(const uint4*)(Blo + gb);
        }
        __syncthreads();

#pragma unroll
        for (int ks = 0; ks < 4; ++ks) {
            const uint32_t kb = (uint32_t)(ks << 5);
            uint32_t bh[4][2], bl[4][2];
#pragma unroll
            for (int np = 0; np < 2; ++np) {
                uint32_t o = kb + (uint32_t)(np * 16 * GSTRIDE * 2);
                LDSM_X4(bh[2 * np][0], bh[2 * np][1], bh[2 * np + 1][0], bh[2 * np + 1][1], sBhi_u + o);
                LDSM_X4(bl[2 * np][0], bl[2 * np][1], bl[2 * np + 1][0], bl[2 * np + 1][1], sBlo_u + o);
            }
            uint32_t ah[4][4], al[4][4];
#pragma unroll
            for (int mt = 0; mt < 4; ++mt) {
                uint32_t o = kb + (uint32_t)(mt * 16 * GSTRIDE * 2);
                LDSM_X4(ah[mt][0], ah[mt][1], ah[mt][2], ah[mt][3], sAhi_u + o);
                LDSM_X4(al[mt][0], al[mt][1], al[mt][2], al[mt][3], sAlo_u + o);
            }
#pragma unroll
            for (int mt = 0; mt < 4; ++mt)
#pragma unroll
                for (int nt = 0; nt < 4; ++nt) {
                    MMA16816(acc[mt][nt], ah[mt], bh[nt]);
                    MMA16816(acc[mt][nt], al[mt], bh[nt]);
                    MMA16816(acc[mt][nt], ah[mt], bl[nt]);
                }
        }
        __syncthreads();
    }

#pragma unroll
    for (int mt = 0; mt < 4; ++mt) {
#pragma unroll
        for (int nt = 0; nt < 4; ++nt) {
            int r0 = m0 + warpM * 64 + mt * 16 + (l >> 2);
            int col = n0 + warpN * 32 + nt * 8 + ((l & 3) << 1);
#pragma unroll
            for (int half = 0; half < 2; ++half) {
                int m = r0 + half * 8;
                float vx = acc[mt][nt][half * 2], vy = acc[mt][nt][half * 2 + 1];
                if (mode == 0) {
                    int which = col >> 10;
                    int c = col & 1023;
                    int h = c >> 6;
                    int d = c & 63;
                    int bb = m >> 11;
                    int t = m & 2047;
                    size_t idx = (size_t)(((bb << 4) | h) * 2048 + t) * 64 + d;
                    uint32_t hp, lp;
                    split2(vx, vy, hp, lp);
                    __nv_bfloat16 *dh_, *dl_;
                    if (which == 0)      { dh_ = g_Qh; dl_ = g_Ql; }
                    else if (which == 1) { dh_ = g_Kh; dl_ = g_Kl; }
                    else                 { dh_ = g_Vh; dl_ = g_Vl; }
                    *(uint32_t*)&dh_[idx] = hp;
                    *(uint32_t*)&dl_[idx] = lp;
                } else {
                    *(float2*)&Out[(size_t)m * 1024 + col] = make_float2(vx, vy);
                }
            }
        }
    }
}

// ---------------------------------------------------------------------------
// Flash attention, HMMA split-bf16, online softmax on fragments.
// CTA: one (b,h), 128 query rows, 8 warps (16 rows each). Bc=64, 32 KV tiles,
// double-buffered via cp.async.
// smem: Qh [0,18432) Ql [18432,36864); stage s at 36864 + s*36864:
//       Kh[0,9216) Kl[+9216) Vh[+18432) Vl[+27648), row stride 72 bf16.
// ---------------------------------------------------------------------------
#define FSTRIDE 144
#define FS_KV 36864
#define FS_STAGE 36864
#define FLASH_SMEM (36864 + 2 * 36864)

__device__ __forceinline__ void kv_issue(int tid, char* sb, int k0,
                                         const __nv_bfloat16* Kh, const __nv_bfloat16* Kl,
                                         const __nv_bfloat16* Vh, const __nv_bfloat16* Vl)
{
#pragma unroll
    for (int t = 0; t < 8; ++t) {
        int ci = tid + (t << 8);          // 0..2047
        int mat = ci >> 9;                // 0 Kh, 1 Kl, 2 Vh, 3 Vl
        int r = (ci & 511) >> 3;
        int q = ci & 7;
        const __nv_bfloat16* src = (mat == 0) ? Kh : (mat == 1) ? Kl : (mat == 2) ? Vh : Vl;
        uint32_t dst = smem_u32(sb + mat * 9216 + r * FSTRIDE + q * 16);
        asm volatile("cp.async.cg.shared.global [%0], [%1], 16;"
                     :: "r"(dst), "l"(src + (size_t)(k0 + r) * 64 + q * 8) : "memory");
    }
    asm volatile("cp.async.commit_group;" ::: "memory");
}

__global__ __launch_bounds__(256, 1) void flash_hmma_kernel()
{
    extern __shared__ char sm[];
    const int tid = threadIdx.x;
    const int w = tid >> 5;
    const int l = tid & 31;
    const int bh = blockIdx.y;
    const int q0 = blockIdx.x << 7;

    const size_t hb = (size_t)bh * 2048 * 64;
    const __nv_bfloat16* Qhp = g_Qh + hb;
    const __nv_bfloat16* Qlp = g_Ql + hb;
    const __nv_bfloat16* Khp = g_Kh + hb;
    const __nv_bfloat16* Klp = g_Kl + hb;
    const __nv_bfloat16* Vhp = g_Vh + hb;
    const __nv_bfloat16* Vlp = g_Vl + hb;

    // load Q tile (hi/lo) into smem
#pragma unroll
    for (int t = 0; t < 8; ++t) {
        int ci = tid + (t << 8);          // 0..2047
        int mat = ci >> 10;               // 0 hi, 1 lo
        int r = (ci & 1023) >> 3;
        int q = ci & 7;
        const __nv_bfloat16* src = mat ? Qlp : Qhp;
        *(uint4*)(sm + mat * 18432 + r * FSTRIDE + q * 16) =
            *(const uint4*)(src + (size_t)(q0 + r) * 64 + q * 8);
    }
    kv_issue(tid, sm + FS_KV, 0, Khp, Klp, Vhp, Vlp);
    __syncthreads();

    // preload Q fragments (A-frag, rows w*16..+15, 4 k-steps)
    uint32_t qh[4][4], ql[4][4];
    {
        uint32_t qb = smem_u32(sm) + (uint32_t)((w * 16 + (l & 15)) * FSTRIDE + ((l >> 4) << 3) * 2);
#pragma unroll
        for (int ks = 0; ks < 4; ++ks) {
            LDSM_X4(qh[ks][0], qh[ks][1], qh[ks][2], qh[ks][3], qb + ks * 32);
            LDSM_X4(ql[ks][0], ql[ks][1], ql[ks][2], ql[ks][3], qb + 18432 + ks * 32);
        }
    }

    float o[8][4];
#pragma unroll
    for (int nt = 0; nt < 8; ++nt)
#pragma unroll
        for (int j = 0; j < 4; ++j) o[nt][j] = 0.f;
    float m_[2] = {-INFINITY, -INFINITY};
    float l_[2] = {0.f, 0.f};

    const uint32_t kb_off = (uint32_t)((((l & 7) + ((l >> 4) << 3)) * FSTRIDE) + (((l >> 3) & 1) << 3) * 2);
    const uint32_t vb_off = (uint32_t)((((l & 7) + (((l >> 3) & 1) << 3)) * FSTRIDE) + ((l >> 4) << 3) * 2);

    for (int jb = 0; jb < 32; ++jb) {
        if (jb + 1 < 32) {
            kv_issue(tid, sm + FS_KV + ((jb + 1) & 1) * FS_STAGE, (jb + 1) << 6, Khp, Klp, Vhp, Vlp);
            asm volatile("cp.async.wait_group 1;" ::: "memory");
        } else {
            asm volatile("cp.async.wait_group 0;" ::: "memory");
        }
        __syncthreads();

        char* sb = sm + FS_KV + (jb & 1) * FS_STAGE;
        const uint32_t kbase_h = smem_u32(sb) + kb_off;
        const uint32_t kbase_l = kbase_h + 9216;
        const uint32_t vbase_h = smem_u32(sb) + 18432 + vb_off;
        const uint32_t vbase_l = vbase_h + 9216;

        // S = Q K^T (3 passes)
        float s[8][4];
#pragma unroll
        for (int nt = 0; nt < 8; ++nt)
#pragma unroll
            for (int j = 0; j < 4; ++j) s[nt][j] = 0.f;

#pragma unroll
        for (int ks = 0; ks < 4; ++ks) {
            uint32_t kh_[8][2], kl_[8][2];
#pragma unroll
            for (int np = 0; np < 4; ++np) {
                uint32_t off = (uint32_t)(np * 16 * FSTRIDE) + ks * 32;
                LDSM_X4(kh_[2 * np][0], kh_[2 * np][1], kh_[2 * np + 1][0], kh_[2 * np + 1][1], kbase_h + off);
                LDSM_X4(kl_[2 * np][0], kl_[2 * np][1], kl_[2 * np + 1][0], kl_[2 * np + 1][1], kbase_l + off);
            }
#pragma unroll
            for (int nt = 0; nt < 8; ++nt) {
                MMA16816(s[nt], qh[ks], kh_[nt]);
                MMA16816(s[nt], ql[ks], kh_[nt]);
                MMA16816(s[nt], qh[ks], kl_[nt]);
            }
        }

        // online softmax (scale 0.125 folded into exp arg)
        float mx[2] = {-INFINITY, -INFINITY};
#pragma unroll
        for (int nt = 0; nt < 8; ++nt) {
            mx[0] = fmaxf(mx[0], fmaxf(s[nt][0], s[nt][1]));
            mx[1] = fmaxf(mx[1], fmaxf(s[nt][2], s[nt][3]));
        }
#pragma unroll
        for (int r = 0; r < 2; ++r) {
            mx[r] = fmaxf(mx[r], __shfl_xor_sync(0xffffffffu, mx[r], 1));
            mx[r] = fmaxf(mx[r], __shfl_xor_sync(0xffffffffu, mx[r], 2));
        }
        float mn[2], al[2], rs[2];
#pragma unroll
        for (int r = 0; r < 2; ++r) {
            mn[r] = fmaxf(m_[r], 0.125f * mx[r]);
            al[r] = __expf(m_[r] - mn[r]);
            m_[r] = mn[r];
            rs[r] = 0.f;
        }
#pragma unroll
        for (int nt = 0; nt < 8; ++nt) {
#pragma unroll
            for (int j = 0; j < 4; ++j) {
                int r = j >> 1;
                float p = __expf(fmaf(s[nt][j], 0.125f, -mn[r]));
                s[nt][j] = p;
                rs[r] += p;
            }
        }
#pragma unroll
        for (int r = 0; r < 2; ++r) {
            rs[r] += __shfl_xor_sync(0xffffffffu, rs[r], 1);
            rs[r] += __shfl_xor_sync(0xffffffffu, rs[r], 2);
            l_[r] = l_[r] * al[r] + rs[r];
        }
#pragma unroll
        for (int nt = 0; nt < 8; ++nt) {
            o[nt][0] *= al[0]; o[nt][1] *= al[0];
            o[nt][2] *= al[1]; o[nt][3] *= al[1];
        }

        // O += P V (3 passes), P fragments packed from registers
#pragma unroll
        for (int ks = 0; ks < 4; ++ks) {
            const int ta = 2 * ks, tb = 2 * ks + 1;
            uint32_t pah[4], pal[4];
            split2(s[ta][0], s[ta][1], pah[0], pal[0]);
            split2(s[ta][2], s[ta][3], pah[1], pal[1]);
            split2(s[tb][0], s[tb][1], pah[2], pal[2]);
            split2(s[tb][2], s[tb][3], pah[3], pal[3]);

            uint32_t vh_[8][2], vl_[8][2];
#pragma unroll
            for (int np = 0; np < 4; ++np) {
                uint32_t off = (uint32_t)(ks * 16 * FSTRIDE) + np * 32;
                LDSM_X4_T(vh_[2 * np][0], vh_[2 * np][1], vh_[2 * np + 1][0], vh_[2 * np + 1][1], vbase_h + off);
                LDSM_X4_T(vl_[2 * np][0], vl_[2 * np][1], vl_[2 * np + 1][0], vl_[2 * np + 1][1], vbase_l + off);
            }
#pragma unroll
            for (int nt = 0; nt < 8; ++nt) {
                MMA16816(o[nt], pah, vh_[nt]);
                MMA16816(o[nt], pal, vh_[nt]);
                MMA16816(o[nt], pah, vl_[nt]);
            }
        }
        __syncthreads();
    }

    // epilogue: Y = O / l, split-bf16, layout [B,T,C]
    const int bb = bh >> 4;
    const int hh = bh & 15;
#pragma unroll
    for (int r = 0; r < 2; ++r) {
        int t = q0 + w * 16 + (l >> 2) + r * 8;
        float inv = 1.f / l_[r];
        size_t rowbase = (size_t)(bb * 2048 + t) * 1024 + hh * 64 + ((l & 3) << 1);
#pragma unroll
        for (int nt = 0; nt < 8; ++nt) {
            uint32_t hp, lp;
            split2(o[nt][2 * r] * inv, o[nt][2 * r + 1] * inv, hp, lp);
            *(uint32_t*)&g_Yhi[rowbase + nt * 8] = hp;
            *(uint32_t*)&g_Ylo[rowbase + nt * 8] = lp;
        }
    }
}

// ---------------------------------------------------------------------------
extern "C" void kernel_launch(void* const* d_in, const int* in_sizes, int n_in,
                              void* d_out, int out_size)
{
    (void)in_sizes; (void)n_in; (void)out_size;
    const float* x = (const float*)d_in[0];
    const float* wq = (const float*)d_in[1];
    const float* wp = (const float*)d_in[2];
    float* out = (float*)d_out;

    cudaFuncSetAttribute(gemm_hmma_kernel, cudaFuncAttributeMaxDynamicSharedMemorySize, GSM_TOTAL);
    cudaFuncSetAttribute(flash_hmma_kernel, cudaFuncAttributeMaxDynamicSharedMemorySize, FLASH_SMEM);

    __nv_bfloat16 *xhi, *xlo, *wqh, *wql, *wph, *wpl, *yhi, *ylo;
    cudaGetSymbolAddress((void**)&xhi, g_Xhi);
    cudaGetSymbolAddress((void**)&xlo, g_Xlo);
    cudaGetSymbolAddress((void**)&wqh, g_Wqh);
    cudaGetSymbolAddress((void**)&wql, g_Wql);
    cudaGetSymbolAddress((void**)&wph, g_Wph);
    cudaGetSymbolAddress((void**)&wpl, g_Wpl);
    cudaGetSymbolAddress((void**)&yhi, g_Yhi);
    cudaGetSymbolAddress((void**)&ylo, g_Ylo);

    split_kernel<<<8192, 256>>>(x, xhi, xlo, 2097152);
    split_kernel<<<3072, 256>>>(wq, wqh, wql, 786432);
    split_kernel<<<1024, 256>>>(wp, wph, wpl, 262144);

    gemm_hmma_kernel<<<dim3(24, 64), 256, GSM_TOTAL>>>(xhi, xlo, wqh, wql, nullptr, 0);
    flash_hmma_kernel<<<dim3(16, 64), 256, FLASH_SMEM>>>();
    gemm_hmma_kernel<<<dim3(8, 64), 256, GSM_TOTAL>>>(yhi, ylo, wph, wpl, out, 1);
}

// round 6
// speedup vs baseline: 4.6481x; 1.2144x over previous
#include <cuda_runtime.h>
#include <cuda_bf16.h>
#include <cuda_fp16.h>
#include <cstdint>
#include <math.h>

// Problem: x[4,2048,1024], W_qkv[3072,1024], W_proj[1024,1024] -> out[4,2048,1024]
#define KDIM 1024

// ---------------- device scratch (allocation-free) ----------------
__device__ __nv_bfloat16 g_Xhi[8388608];
__device__ __nv_bfloat16 g_Xlo[8388608];
__device__ __nv_bfloat16 g_Wqh[3145728];
__device__ __nv_bfloat16 g_Wql[3145728];
__device__ __nv_bfloat16 g_Wph[1048576];
__device__ __nv_bfloat16 g_Wpl[1048576];
__device__ __half g_Qf[8388608];    // pre-scaled by 0.125
__device__ __half g_Kf[8388608];
__device__ __half g_Vhf[8388608];
__device__ __half g_Vlf[8388608];
__device__ __nv_bfloat16 g_Yhi[8388608];
__device__ __nv_bfloat16 g_Ylo[8388608];

__device__ __forceinline__ uint32_t smem_u32(const void* p) {
    uint32_t a;
    asm("{ .reg .u64 t; cvta.to.shared.u64 t, %1; cvt.u32.u64 %0, t; }" : "=r"(a) : "l"(p));
    return a;
}

#define LDSM_X4(r0, r1, r2, r3, addr) \
    asm volatile("ldmatrix.sync.aligned.m8n8.x4.shared.b16 {%0,%1,%2,%3}, [%4];" \
                 : "=r"(r0), "=r"(r1), "=r"(r2), "=r"(r3) : "r"(addr))

#define LDSM_X4_T(r0, r1, r2, r3, addr) \
    asm volatile("ldmatrix.sync.aligned.m8n8.x4.trans.shared.b16 {%0,%1,%2,%3}, [%4];" \
                 : "=r"(r0), "=r"(r1), "=r"(r2), "=r"(r3) : "r"(addr))

#define MMA16816(c, a, b) \
    asm volatile("mma.sync.aligned.m16n8k16.row.col.f32.bf16.bf16.f32 " \
                 "{%0,%1,%2,%3}, {%4,%5,%6,%7}, {%8,%9}, {%0,%1,%2,%3};" \
                 : "+f"((c)[0]), "+f"((c)[1]), "+f"((c)[2]), "+f"((c)[3]) \
                 : "r"((a)[0]), "r"((a)[1]), "r"((a)[2]), "r"((a)[3]), \
                   "r"((b)[0]), "r"((b)[1]))

#define MMA16816F(c, a, b) \
    asm volatile("mma.sync.aligned.m16n8k16.row.col.f32.f16.f16.f32 " \
                 "{%0,%1,%2,%3}, {%4,%5,%6,%7}, {%8,%9}, {%0,%1,%2,%3};" \
                 : "+f"((c)[0]), "+f"((c)[1]), "+f"((c)[2]), "+f"((c)[3]) \
                 : "r"((a)[0]), "r"((a)[1]), "r"((a)[2]), "r"((a)[3]), \
                   "r"((b)[0]), "r"((b)[1]))

#define CP_ASYNC16(dst, src) \
    asm volatile("cp.async.cg.shared.global [%0], [%1], 16;" :: "r"(dst), "l"(src) : "memory")
#define CP_COMMIT() asm volatile("cp.async.commit_group;" ::: "memory")
#define CP_WAIT1()  asm volatile("cp.async.wait_group 1;" ::: "memory")
#define CP_WAIT0()  asm volatile("cp.async.wait_group 0;" ::: "memory")

// split pair (a,b) -> bf16x2 hi (truncated top-16-bits), bf16x2 lo (exact residual)
__device__ __forceinline__ void split2(float a, float b, uint32_t& hp, uint32_t& lp) {
    uint32_t ua = __float_as_uint(a), ub = __float_as_uint(b);
    hp = __byte_perm(ua, ub, 0x7632);
    float la = a - __uint_as_float(ua & 0xFFFF0000u);
    float lb = b - __uint_as_float(ub & 0xFFFF0000u);
    __nv_bfloat162 t = __float22bfloat162_rn(make_float2(la, lb));
    lp = *(uint32_t*)&t;
}

// ---------------------------------------------------------------------------
// split kernel: fp32 -> (bf16 hi, bf16 lo)
// ---------------------------------------------------------------------------
__global__ __launch_bounds__(256) void split_kernel(const float* __restrict__ src,
                                                    __nv_bfloat16* __restrict__ hi,
                                                    __nv_bfloat16* __restrict__ lo,
                                                    int n4)
{
    int i = blockIdx.x * blockDim.x + threadIdx.x;
    if (i >= n4) return;
    float4 v = ((const float4*)src)[i];
    uint32_t h0, l0, h1, l1;
    split2(v.x, v.y, h0, l0);
    split2(v.z, v.w, h1, l1);
    ((uint2*)hi)[i] = make_uint2(h0, h1);
    ((uint2*)lo)[i] = make_uint2(l0, l1);
}

// ---------------------------------------------------------------------------
// HMMA split-bf16 GEMM, 2-stage cp.async pipeline.
// CTA 128x128, 8 warps (2M x 4N), K_tile=64, 16 iters.
// mode 0: QKV -> Qf (x0.125 fp16), Kf (fp16), V (fp16 hi/lo)
// mode 1: row-major fp32 Out
// ---------------------------------------------------------------------------
#define GTILE  (128 * 144)          // 18432 B per matrix tile
#define GSTAGE (4 * GTILE)          // 73728 B
#define GSM_TOTAL (2 * GSTAGE)      // 147456 B

__global__ __launch_bounds__(256)
void gemm_hmma_kernel(const __nv_bfloat16* __restrict__ Ahi,
                      const __nv_bfloat16* __restrict__ Alo,
                      const __nv_bfloat16* __restrict__ Bhi,
                      const __nv_bfloat16* __restrict__ Blo,
                      float* __restrict__ Out, int mode)
{
    extern __shared__ char smem[];
    const int tid = threadIdx.x;
    const int wid = tid >> 5;
    const int l = tid & 31;
    const int m0 = blockIdx.y << 7;
    const int n0 = blockIdx.x << 7;
    const int warpM = wid >> 2;
    const int warpN = wid & 3;

    float acc[4][4][4];
#pragma unroll
    for (int i = 0; i < 4; ++i)
#pragma unroll
        for (int j = 0; j < 4; ++j)
#pragma unroll
            for (int k = 0; k < 4; ++k) acc[i][j][k] = 0.f;

    const int aRow = warpM * 64 + (l & 15);
    const uint32_t aOff = (uint32_t)(aRow * 144 + (((l >> 4) << 3) << 1));
    const int bRow = warpN * 32 + (l & 7) + ((l >> 4) << 3);
    const uint32_t bOff = (uint32_t)(bRow * 144 + ((((l >> 3) & 1) << 3) << 1));
    const uint32_t smb = smem_u32(smem);

    // ---- stage issue: 4096 16B chunks, 16 per thread ----
    auto issue = [&](int stg, int k0) {
        char* st = smem + stg * GSTAGE;
#pragma unroll
        for (int t = 0; t < 16; ++t) {
            int ci = tid + (t << 8);
            int mat = ci >> 10;
            int pos = ci & 1023;
            int row = pos >> 3;
            int q = pos & 7;
            const __nv_bfloat16* src = (mat == 0) ? Ahi : (mat == 1) ? Alo : (mat == 2) ? Bhi : Blo;
            int grow = ((mat < 2) ? m0 : n0) + row;
            uint32_t dst = smem_u32(st + mat * GTILE + row * 144 + (q << 4));
            CP_ASYNC16(dst, src + (size_t)grow * KDIM + k0 + (q << 3));
        }
        CP_COMMIT();
    };

    issue(0, 0);
    for (int iter = 0; iter < 16; ++iter) {
        if (iter < 15) {
            issue((iter + 1) & 1, (iter + 1) << 6);
            CP_WAIT1();
        } else {
            CP_WAIT0();
        }
        __syncthreads();

        const uint32_t sb = smb + (iter & 1) * GSTAGE;
        const uint32_t sAhi_u = sb + aOff;
        const uint32_t sAlo_u = sAhi_u + GTILE;
        const uint32_t sBhi_u = sb + 2 * GTILE + bOff;
        const uint32_t sBlo_u = sBhi_u + GTILE;

#pragma unroll
        for (int ks = 0; ks < 4; ++ks) {
            const uint32_t kb = (uint32_t)(ks << 5);
            uint32_t bh[4][2], bl[4][2];
#pragma unroll
            for (int np = 0; np < 2; ++np) {
                uint32_t o = kb + (uint32_t)(np * 16 * 144);
                LDSM_X4(bh[2 * np][0], bh[2 * np][1], bh[2 * np + 1][0], bh[2 * np + 1][1], sBhi_u + o);
                LDSM_X4(bl[2 * np][0], bl[2 * np][1], bl[2 * np + 1][0], bl[2 * np + 1][1], sBlo_u + o);
            }
            uint32_t ah[4][4], al[4][4];
#pragma unroll
            for (int mt = 0; mt < 4; ++mt) {
                uint32_t o = kb + (uint32_t)(mt * 16 * 144);
                LDSM_X4(ah[mt][0], ah[mt][1], ah[mt][2], ah[mt][3], sAhi_u + o);
                LDSM_X4(al[mt][0], al[mt][1], al[mt][2], al[mt][3], sAlo_u + o);
            }
#pragma unroll
            for (int mt = 0; mt < 4; ++mt)
#pragma unroll
                for (int nt = 0; nt < 4; ++nt) {
                    MMA16816(acc[mt][nt], ah[mt], bh[nt]);
                    MMA16816(acc[mt][nt], al[mt], bh[nt]);
                    MMA16816(acc[mt][nt], ah[mt], bl[nt]);
                }
        }
        __syncthreads();
    }

    // ---- epilogue ----
#pragma unroll
    for (int mt = 0; mt < 4; ++mt) {
#pragma unroll
        for (int nt = 0; nt < 4; ++nt) {
            int r0 = m0 + warpM * 64 + mt * 16 + (l >> 2);
            int col = n0 + warpN * 32 + nt * 8 + ((l & 3) << 1);
#pragma unroll
            for (int half = 0; half < 2; ++half) {
                int m = r0 + half * 8;
                float vx = acc[mt][nt][half * 2], vy = acc[mt][nt][half * 2 + 1];
                if (mode == 0) {
                    int which = col >> 10;
                    int c = col & 1023;
                    int h = c >> 6;
                    int d = c & 63;
                    int bb = m >> 11;
                    int t = m & 2047;
                    size_t idx = (size_t)(((bb << 4) | h) * 2048 + t) * 64 + d;
                    if (which == 0) {
                        __half2 q2 = __floats2half2_rn(vx * 0.125f, vy * 0.125f);
                        *(__half2*)&g_Qf[idx] = q2;
                    } else if (which == 1) {
                        *(__half2*)&g_Kf[idx] = __floats2half2_rn(vx, vy);
                    } else {
                        __half hx = __float2half_rn(vx), hy = __float2half_rn(vy);
                        float lx = vx - __half2float(hx), ly = vy - __half2float(hy);
                        *(__half2*)&g_Vhf[idx] = __halves2half2(hx, hy);
                        *(__half2*)&g_Vlf[idx] = __floats2half2_rn(lx, ly);
                    }
                } else {
                    *(float2*)&Out[(size_t)m * 1024 + col] = make_float2(vx, vy);
                }
            }
        }
    }
}

// ---------------------------------------------------------------------------
// Flash attention, fp16 HMMA: S = (Q/8)K single pass; O += P(Vh+Vl) 2 passes.
// CTA: one (b,h) x 128 rows, 8 warps x 16 rows. Bc=64, double-buffered cp.async.
// smem: Qf [0,18432); stage s at 18432 + s*27648: K[0,9216) Vh[+9216) Vl[+18432)
// ---------------------------------------------------------------------------
#define FQ_SZ 18432
#define FSTAGE 27648
#define FLASH_SMEM (FQ_SZ + 2 * FSTAGE)   // 73728

__device__ __forceinline__ void kv_issue(int tid, char* sb, int k0,
                                         const __half* Kf, const __half* Vh, const __half* Vl)
{
#pragma unroll
    for (int t = 0; t < 6; ++t) {
        int ci = tid + (t << 8);          // 0..1535
        int mat = ci >> 9;                // 0 K, 1 Vh, 2 Vl
        int r = (ci & 511) >> 3;
        int q = ci & 7;
        const __half* src = (mat == 0) ? Kf : (mat == 1) ? Vh : Vl;
        uint32_t dst = smem_u32(sb + mat * 9216 + r * 144 + (q << 4));
        CP_ASYNC16(dst, src + (size_t)(k0 + r) * 64 + (q << 3));
    }
    CP_COMMIT();
}

__global__ __launch_bounds__(256) void flash_hmma_kernel()
{
    extern __shared__ char sm[];
    const int tid = threadIdx.x;
    const int w = tid >> 5;
    const int l = tid & 31;
    const int bh = blockIdx.y;
    const int q0 = blockIdx.x << 7;

    const size_t hb = (size_t)bh * 2048 * 64;
    const __half* Qp = g_Qf + hb;
    const __half* Kp = g_Kf + hb;
    const __half* Vhp = g_Vhf + hb;
    const __half* Vlp = g_Vlf + hb;

    // Q tile (fp16, pre-scaled) -> smem
#pragma unroll
    for (int t = 0; t < 4; ++t) {
        int ci = tid + (t << 8);          // 0..1023
        int r = ci >> 3;
        int q = ci & 7;
        *(uint4*)(sm + r * 144 + (q << 4)) = *(const uint4*)(Qp + (size_t)(q0 + r) * 64 + (q << 3));
    }
    kv_issue(tid, sm + FQ_SZ, 0, Kp, Vhp, Vlp);
    __syncthreads();

    // Q fragments (A-frag, rows w*16..+15, 4 k-steps)
    uint32_t qf[4][4];
    {
        uint32_t qb = smem_u32(sm) + (uint32_t)((w * 16 + (l & 15)) * 144 + (((l >> 4) << 3) << 1));
#pragma unroll
        for (int ks = 0; ks < 4; ++ks)
            LDSM_X4(qf[ks][0], qf[ks][1], qf[ks][2], qf[ks][3], qb + ks * 32);
    }

    float o[8][4];
#pragma unroll
    for (int nt = 0; nt < 8; ++nt)
#pragma unroll
        for (int j = 0; j < 4; ++j) o[nt][j] = 0.f;
    float m_[2] = {-INFINITY, -INFINITY};
    float l_[2] = {0.f, 0.f};

    const uint32_t kb_off = (uint32_t)((((l & 7) + ((l >> 4) << 3)) * 144) + ((((l >> 3) & 1) << 3) << 1));
    const uint32_t vb_off = (uint32_t)((((l & 7) + (((l >> 3) & 1) << 3)) * 144) + (((l >> 4) << 3) << 1));

    for (int jb = 0; jb < 32; ++jb) {
        if (jb + 1 < 32) {
            kv_issue(tid, sm + FQ_SZ + ((jb + 1) & 1) * FSTAGE, (jb + 1) << 6, Kp, Vhp, Vlp);
            CP_WAIT1();
        } else {
            CP_WAIT0();
        }
        __syncthreads();

        char* sb = sm + FQ_SZ + (jb & 1) * FSTAGE;
        const uint32_t kbase = smem_u32(sb) + kb_off;
        const uint32_t vbase_h = smem_u32(sb) + 9216 + vb_off;
        const uint32_t vbase_l = vbase_h + 9216;

        // S = Q K^T (single fp16 pass; Q pre-scaled)
        float s[8][4];
#pragma unroll
        for (int nt = 0; nt < 8; ++nt)
#pragma unroll
            for (int j = 0; j < 4; ++j) s[nt][j] = 0.f;

#pragma unroll
        for (int ks = 0; ks < 4; ++ks) {
            uint32_t kh_[8][2];
#pragma unroll
            for (int np = 0; np < 4; ++np) {
                uint32_t off = (uint32_t)(np * 16 * 144) + ks * 32;
                LDSM_X4(kh_[2 * np][0], kh_[2 * np][1], kh_[2 * np + 1][0], kh_[2 * np + 1][1], kbase + off);
            }
#pragma unroll
            for (int nt = 0; nt < 8; ++nt)
                MMA16816F(s[nt], qf[ks], kh_[nt]);
        }

        // online softmax (logits already scaled)
        float mx[2] = {-INFINITY, -INFINITY};
#pragma unroll
        for (int nt = 0; nt < 8; ++nt) {
            mx[0] = fmaxf(mx[0], fmaxf(s[nt][0], s[nt][1]));
            mx[1] = fmaxf(mx[1], fmaxf(s[nt][2], s[nt][3]));
        }
#pragma unroll
        for (int r = 0; r < 2; ++r) {
            mx[r] = fmaxf(mx[r], __shfl_xor_sync(0xffffffffu, mx[r], 1));
            mx[r] = fmaxf(mx[r], __shfl_xor_sync(0xffffffffu, mx[r], 2));
        }
        float mn[2], al[2], rs[2];
#pragma unroll
        for (int r = 0; r < 2; ++r) {
            mn[r] = fmaxf(m_[r], mx[r]);
            al[r] = __expf(m_[r] - mn[r]);
            m_[r] = mn[r];
            rs[r] = 0.f;
        }
#pragma unroll
        for (int nt = 0; nt < 8; ++nt) {
#pragma unroll
            for (int j = 0; j < 4; ++j) {
                int r = j >> 1;
                float p = __expf(s[nt][j] - mn[r]);
                s[nt][j] = p;
                rs[r] += p;
            }
        }
#pragma unroll
        for (int r = 0; r < 2; ++r) {
            rs[r] += __shfl_xor_sync(0xffffffffu, rs[r], 1);
            rs[r] += __shfl_xor_sync(0xffffffffu, rs[r], 2);
            l_[r] = l_[r] * al[r] + rs[r];
        }
#pragma unroll
        for (int nt = 0; nt < 8; ++nt) {
            o[nt][0] *= al[0]; o[nt][1] *= al[0];
            o[nt][2] *= al[1]; o[nt][3] *= al[1];
        }

        // O += P V (P fp16 single, V hi+lo)
#pragma unroll
        for (int ks = 0; ks < 4; ++ks) {
            const int ta = 2 * ks, tb = 2 * ks + 1;
            uint32_t pa[4];
            {
                __half2 p0 = __floats2half2_rn(s[ta][0], s[ta][1]);
                __half2 p1 = __floats2half2_rn(s[ta][2], s[ta][3]);
                __half2 p2 = __floats2half2_rn(s[tb][0], s[tb][1]);
                __half2 p3 = __floats2half2_rn(s[tb][2], s[tb][3]);
                pa[0] = *(uint32_t*)&p0; pa[1] = *(uint32_t*)&p1;
                pa[2] = *(uint32_t*)&p2; pa[3] = *(uint32_t*)&p3;
            }
            uint32_t vh_[8][2], vl_[8][2];
#pragma unroll
            for (int np = 0; np < 4; ++np) {
                uint32_t off = (uint32_t)(ks * 16 * 144) + np * 32;
                LDSM_X4_T(vh_[2 * np][0], vh_[2 * np][1], vh_[2 * np + 1][0], vh_[2 * np + 1][1], vbase_h + off);
                LDSM_X4_T(vl_[2 * np][0], vl_[2 * np][1], vl_[2 * np + 1][0], vl_[2 * np + 1][1], vbase_l + off);
            }
#pragma unroll
            for (int nt = 0; nt < 8; ++nt) {
                MMA16816F(o[nt], pa, vh_[nt]);
                MMA16816F(o[nt], pa, vl_[nt]);
            }
        }
        __syncthreads();
    }

    // epilogue: Y = O / l, split-bf16, layout [B,T,C]
    const int bb = bh >> 4;
    const int hh = bh & 15;
#pragma unroll
    for (int r = 0; r < 2; ++r) {
        int t = q0 + w * 16 + (l >> 2) + r * 8;
        float inv = 1.f / l_[r];
        size_t rowbase = (size_t)(bb * 2048 + t) * 1024 + hh * 64 + ((l & 3) << 1);
#pragma unroll
        for (int nt = 0; nt < 8; ++nt) {
            uint32_t hp, lp;
            split2(o[nt][2 * r] * inv, o[nt][2 * r + 1] * inv, hp, lp);
            *(uint32_t*)&g_Yhi[rowbase + nt * 8] = hp;
            *(uint32_t*)&g_Ylo[rowbase + nt * 8] = lp;
        }
    }
}

// ---------------------------------------------------------------------------
extern "C" void kernel_launch(void* const* d_in, const int* in_sizes, int n_in,
                              void* d_out, int out_size)
{
    (void)in_sizes; (void)n_in; (void)out_size;
    const float* x = (const float*)d_in[0];
    const float* wq = (const float*)d_in[1];
    const float* wp = (const float*)d_in[2];
    float* out = (float*)d_out;

    cudaFuncSetAttribute(gemm_hmma_kernel, cudaFuncAttributeMaxDynamicSharedMemorySize, GSM_TOTAL);
    cudaFuncSetAttribute(flash_hmma_kernel, cudaFuncAttributeMaxDynamicSharedMemorySize, FLASH_SMEM);

    __nv_bfloat16 *xhi, *xlo, *wqh, *wql, *wph, *wpl, *yhi, *ylo;
    cudaGetSymbolAddress((void**)&xhi, g_Xhi);
    cudaGetSymbolAddress((void**)&xlo, g_Xlo);
    cudaGetSymbolAddress((void**)&wqh, g_Wqh);
    cudaGetSymbolAddress((void**)&wql, g_Wql);
    cudaGetSymbolAddress((void**)&wph, g_Wph);
    cudaGetSymbolAddress((void**)&wpl, g_Wpl);
    cudaGetSymbolAddress((void**)&yhi, g_Yhi);
    cudaGetSymbolAddress((void**)&ylo, g_Ylo);

    split_kernel<<<8192, 256>>>(x, xhi, xlo, 2097152);
    split_kernel<<<3072, 256>>>(wq, wqh, wql, 786432);
    split_kernel<<<1024, 256>>>(wp, wph, wpl, 262144);

    gemm_hmma_kernel<<<dim3(24, 64), 256, GSM_TOTAL>>>(xhi, xlo, wqh, wql, nullptr, 0);
    flash_hmma_kernel<<<dim3(16, 64), 256, FLASH_SMEM>>>();
    gemm_hmma_kernel<<<dim3(8, 64), 256, GSM_TOTAL>>>(yhi, ylo, wph, wpl, out, 1);
}

// round 7
// speedup vs baseline: 6.8220x; 1.4677x over previous
#include <cuda_runtime.h>
#include <cuda_fp16.h>
#include <cstdint>
#include <math.h>

// Problem: x[4,2048,1024], W_qkv[3072,1024], W_proj[1024,1024] -> out[4,2048,1024]
#define KDIM 1024

// ---------------- device scratch (allocation-free) ----------------
__device__ __half g_Xh[8388608];
__device__ __half g_Xl[8388608];
__device__ __half g_Wqf[3145728];
__device__ __half g_Wpf[1048576];
__device__ __half g_Qf[8388608];    // pre-scaled by 0.125
__device__ __half g_Kf[8388608];
__device__ __half g_Vf[8388608];
__device__ __half g_Yh[8388608];
__device__ __half g_Yl[8388608];

__device__ __forceinline__ uint32_t smem_u32(const void* p) {
    uint32_t a;
    asm("{ .reg .u64 t; cvta.to.shared.u64 t, %1; cvt.u32.u64 %0, t; }" : "=r"(a) : "l"(p));
    return a;
}

#define LDSM_X4(r0, r1, r2, r3, addr) \
    asm volatile("ldmatrix.sync.aligned.m8n8.x4.shared.b16 {%0,%1,%2,%3}, [%4];" \
                 : "=r"(r0), "=r"(r1), "=r"(r2), "=r"(r3) : "r"(addr))

#define LDSM_X4_T(r0, r1, r2, r3, addr) \
    asm volatile("ldmatrix.sync.aligned.m8n8.x4.trans.shared.b16 {%0,%1,%2,%3}, [%4];" \
                 : "=r"(r0), "=r"(r1), "=r"(r2), "=r"(r3) : "r"(addr))

#define MMA16816F(c, a, b) \
    asm volatile("mma.sync.aligned.m16n8k16.row.col.f32.f16.f16.f32 " \
                 "{%0,%1,%2,%3}, {%4,%5,%6,%7}, {%8,%9}, {%0,%1,%2,%3};" \
                 : "+f"((c)[0]), "+f"((c)[1]), "+f"((c)[2]), "+f"((c)[3]) \
                 : "r"((a)[0]), "r"((a)[1]), "r"((a)[2]), "r"((a)[3]), \
                   "r"((b)[0]), "r"((b)[1]))

#define CP_ASYNC16(dst, src) \
    asm volatile("cp.async.cg.shared.global [%0], [%1], 16;" :: "r"(dst), "l"(src) : "memory")
#define CP_COMMIT() asm volatile("cp.async.commit_group;" ::: "memory")
#define CP_WAIT1()  asm volatile("cp.async.wait_group 1;" ::: "memory")
#define CP_WAIT0()  asm volatile("cp.async.wait_group 0;" ::: "memory")

// fp16 split: hi = fp16(v), lo = fp16(v - hi)
__device__ __forceinline__ void splitH2(float a, float b, uint32_t& hp, uint32_t& lp) {
    __half ha = __float2half_rn(a), hb = __float2half_rn(b);
    float la = a - __half2float(ha), lb = b - __half2float(hb);
    __half2 h = __halves2half2(ha, hb);
    __half2 l = __floats2half2_rn(la, lb);
    hp = *(uint32_t*)&h;
    lp = *(uint32_t*)&l;
}

// ---------------------------------------------------------------------------
// split16: fp32 -> fp16 hi/lo          conv16: fp32 -> fp16
// ---------------------------------------------------------------------------
__global__ __launch_bounds__(256) void split16_kernel(const float* __restrict__ src,
                                                      __half* __restrict__ hi,
                                                      __half* __restrict__ lo, int n4)
{
    int i = blockIdx.x * blockDim.x + threadIdx.x;
    if (i >= n4) return;
    float4 v = ((const float4*)src)[i];
    uint32_t h0, l0, h1, l1;
    splitH2(v.x, v.y, h0, l0);
    splitH2(v.z, v.w, h1, l1);
    ((uint2*)hi)[i] = make_uint2(h0, h1);
    ((uint2*)lo)[i] = make_uint2(l0, l1);
}

__global__ __launch_bounds__(256) void conv16_kernel(const float* __restrict__ src,
                                                     __half* __restrict__ dst, int n4)
{
    int i = blockIdx.x * blockDim.x + threadIdx.x;
    if (i >= n4) return;
    float4 v = ((const float4*)src)[i];
    __half2 a = __floats2half2_rn(v.x, v.y);
    __half2 b = __floats2half2_rn(v.z, v.w);
    ((uint2*)dst)[i] = make_uint2(*(uint32_t*)&a, *(uint32_t*)&b);
}

// ---------------------------------------------------------------------------
// HMMA fp16 asymmetric 2-pass GEMM: C = (Ah + Al) * B^T, fp32 accumulate.
// CTA 128x128, 8 warps (2M x 4N), K_tile=64, 16 iters, 2-stage cp.async.
// mode 0: QKV -> Qf(x0.125), Kf, Vf (single fp16)
// mode 1: row-major fp32 Out
// ---------------------------------------------------------------------------
#define GTILE  (128 * 144)           // 18432 B
#define GSTAGE (3 * GTILE)           // 55296 B: Ah, Al, B
#define GSM_TOTAL (2 * GSTAGE)       // 110592 B

__global__ __launch_bounds__(256, 2)
void gemm_hmma_kernel(const __half* __restrict__ Ah,
                      const __half* __restrict__ Al,
                      const __half* __restrict__ B,
                      float* __restrict__ Out, int mode)
{
    extern __shared__ char smem[];
    const int tid = threadIdx.x;
    const int wid = tid >> 5;
    const int l = tid & 31;
    const int m0 = blockIdx.y << 7;
    const int n0 = blockIdx.x << 7;
    const int warpM = wid >> 2;
    const int warpN = wid & 3;

    float acc[4][4][4];
#pragma unroll
    for (int i = 0; i < 4; ++i)
#pragma unroll
        for (int j = 0; j < 4; ++j)
#pragma unroll
            for (int k = 0; k < 4; ++k) acc[i][j][k] = 0.f;

    const int aRow = warpM * 64 + (l & 15);
    const uint32_t aOff = (uint32_t)(aRow * 144 + (((l >> 4) << 3) << 1));
    const int bRow = warpN * 32 + (l & 7) + ((l >> 4) << 3);
    const uint32_t bOff = (uint32_t)(bRow * 144 + ((((l >> 3) & 1) << 3) << 1));
    const uint32_t smb = smem_u32(smem);

    // stage issue: 3072 16B chunks, 12 per thread
    auto issue = [&](int stg, int k0) {
        char* st = smem + stg * GSTAGE;
#pragma unroll
        for (int t = 0; t < 12; ++t) {
            int ci = tid + (t << 8);         // 0..3071
            int mat = ci >> 10;              // 0 Ah, 1 Al, 2 B
            int pos = ci & 1023;
            int row = pos >> 3;
            int q = pos & 7;
            const __half* src = (mat == 0) ? Ah : (mat == 1) ? Al : B;
            int grow = ((mat < 2) ? m0 : n0) + row;
            uint32_t dst = smem_u32(st + mat * GTILE + row * 144 + (q << 4));
            CP_ASYNC16(dst, src + (size_t)grow * KDIM + k0 + (q << 3));
        }
        CP_COMMIT();
    };

    issue(0, 0);
    for (int iter = 0; iter < 16; ++iter) {
        if (iter < 15) {
            issue((iter + 1) & 1, (iter + 1) << 6);
            CP_WAIT1();
        } else {
            CP_WAIT0();
        }
        __syncthreads();

        const uint32_t sb = smb + (iter & 1) * GSTAGE;
        const uint32_t sAh_u = sb + aOff;
        const uint32_t sAl_u = sAh_u + GTILE;
        const uint32_t sB_u = sb + 2 * GTILE + bOff;

#pragma unroll
        for (int ks = 0; ks < 4; ++ks) {
            const uint32_t kb = (uint32_t)(ks << 5);
            uint32_t bf[4][2];
#pragma unroll
            for (int np = 0; np < 2; ++np) {
                uint32_t o = kb + (uint32_t)(np * 16 * 144);
                LDSM_X4(bf[2 * np][0], bf[2 * np][1], bf[2 * np + 1][0], bf[2 * np + 1][1], sB_u + o);
            }
            uint32_t ah[4][4], al[4][4];
#pragma unroll
            for (int mt = 0; mt < 4; ++mt) {
                uint32_t o = kb + (uint32_t)(mt * 16 * 144);
                LDSM_X4(ah[mt][0], ah[mt][1], ah[mt][2], ah[mt][3], sAh_u + o);
                LDSM_X4(al[mt][0], al[mt][1], al[mt][2], al[mt][3], sAl_u + o);
            }
#pragma unroll
            for (int mt = 0; mt < 4; ++mt)
#pragma unroll
                for (int nt = 0; nt < 4; ++nt) {
                    MMA16816F(acc[mt][nt], ah[mt], bf[nt]);
                    MMA16816F(acc[mt][nt], al[mt], bf[nt]);
                }
        }
        __syncthreads();
    }

    // epilogue
#pragma unroll
    for (int mt = 0; mt < 4; ++mt) {
#pragma unroll
        for (int nt = 0; nt < 4; ++nt) {
            int r0 = m0 + warpM * 64 + mt * 16 + (l >> 2);
            int col = n0 + warpN * 32 + nt * 8 + ((l & 3) << 1);
#pragma unroll
            for (int half = 0; half < 2; ++half) {
                int m = r0 + half * 8;
                float vx = acc[mt][nt][half * 2], vy = acc[mt][nt][half * 2 + 1];
                if (mode == 0) {
                    int which = col >> 10;
                    int c = col & 1023;
                    int h = c >> 6;
                    int d = c & 63;
                    int bb = m >> 11;
                    int t = m & 2047;
                    size_t idx = (size_t)(((bb << 4) | h) * 2048 + t) * 64 + d;
                    if (which == 0) {
                        __half2 q2 = __floats2half2_rn(vx * 0.125f, vy * 0.125f);
                        *(__half2*)&g_Qf[idx] = q2;
                    } else if (which == 1) {
                        *(__half2*)&g_Kf[idx] = __floats2half2_rn(vx, vy);
                    } else {
                        *(__half2*)&g_Vf[idx] = __floats2half2_rn(vx, vy);
                    }
                } else {
                    *(float2*)&Out[(size_t)m * 1024 + col] = make_float2(vx, vy);
                }
            }
        }
    }
}

// ---------------------------------------------------------------------------
// Flash attention, fp16 HMMA: S = (Q/8)K 1 pass; O += P V 1 pass.
// CTA: one (b,h) x 128 rows, 8 warps x 16 rows. Bc=64, double-buffered cp.async.
// smem: Qf [0,18432); stage s at 18432 + s*18432: K[0,9216) V[9216,18432)
// ---------------------------------------------------------------------------
#define FQ_SZ 18432
#define FSTAGE 18432
#define FLASH_SMEM (FQ_SZ + 2 * FSTAGE)   // 55296

__device__ __forceinline__ void kv_issue(int tid, char* sb, int k0,
                                         const __half* Kf, const __half* Vf)
{
#pragma unroll
    for (int t = 0; t < 4; ++t) {
        int ci = tid + (t << 8);          // 0..1023
        int mat = ci >> 9;                // 0 K, 1 V
        int r = (ci & 511) >> 3;
        int q = ci & 7;
        const __half* src = mat ? Vf : Kf;
        uint32_t dst = smem_u32(sb + mat * 9216 + r * 144 + (q << 4));
        CP_ASYNC16(dst, src + (size_t)(k0 + r) * 64 + (q << 3));
    }
    CP_COMMIT();
}

__global__ __launch_bounds__(256, 2) void flash_hmma_kernel()
{
    extern __shared__ char sm[];
    const int tid = threadIdx.x;
    const int w = tid >> 5;
    const int l = tid & 31;
    const int bh = blockIdx.y;
    const int q0 = blockIdx.x << 7;

    const size_t hb = (size_t)bh * 2048 * 64;
    const __half* Qp = g_Qf + hb;
    const __half* Kp = g_Kf + hb;
    const __half* Vp = g_Vf + hb;

    // Q tile -> smem
#pragma unroll
    for (int t = 0; t < 4; ++t) {
        int ci = tid + (t << 8);
        int r = ci >> 3;
        int q = ci & 7;
        *(uint4*)(sm + r * 144 + (q << 4)) = *(const uint4*)(Qp + (size_t)(q0 + r) * 64 + (q << 3));
    }
    kv_issue(tid, sm + FQ_SZ, 0, Kp, Vp);
    __syncthreads();

    uint32_t qf[4][4];
    {
        uint32_t qb = smem_u32(sm) + (uint32_t)((w * 16 + (l & 15)) * 144 + (((l >> 4) << 3) << 1));
#pragma unroll
        for (int ks = 0; ks < 4; ++ks)
            LDSM_X4(qf[ks][0], qf[ks][1], qf[ks][2], qf[ks][3], qb + ks * 32);
    }

    float o[8][4];
#pragma unroll
    for (int nt = 0; nt < 8; ++nt)
#pragma unroll
        for (int j = 0; j < 4; ++j) o[nt][j] = 0.f;
    float m_[2] = {-INFINITY, -INFINITY};
    float l_[2] = {0.f, 0.f};

    const uint32_t kb_off = (uint32_t)((((l & 7) + ((l >> 4) << 3)) * 144) + ((((l >> 3) & 1) << 3) << 1));
    const uint32_t vb_off = (uint32_t)((((l & 7) + (((l >> 3) & 1) << 3)) * 144) + (((l >> 4) << 3) << 1));

    for (int jb = 0; jb < 32; ++jb) {
        if (jb + 1 < 32) {
            kv_issue(tid, sm + FQ_SZ + ((jb + 1) & 1) * FSTAGE, (jb + 1) << 6, Kp, Vp);
            CP_WAIT1();
        } else {
            CP_WAIT0();
        }
        __syncthreads();

        char* sb = sm + FQ_SZ + (jb & 1) * FSTAGE;
        const uint32_t kbase = smem_u32(sb) + kb_off;
        const uint32_t vbase = smem_u32(sb) + 9216 + vb_off;

        // S = Q K^T (1 pass; Q pre-scaled)
        float s[8][4];
#pragma unroll
        for (int nt = 0; nt < 8; ++nt)
#pragma unroll
            for (int j = 0; j < 4; ++j) s[nt][j] = 0.f;

#pragma unroll
        for (int ks = 0; ks < 4; ++ks) {
            uint32_t kh_[8][2];
#pragma unroll
            for (int np = 0; np < 4; ++np) {
                uint32_t off = (uint32_t)(np * 16 * 144) + ks * 32;
                LDSM_X4(kh_[2 * np][0], kh_[2 * np][1], kh_[2 * np + 1][0], kh_[2 * np + 1][1], kbase + off);
            }
#pragma unroll
            for (int nt = 0; nt < 8; ++nt)
                MMA16816F(s[nt], qf[ks], kh_[nt]);
        }

        // online softmax
        float mx[2] = {-INFINITY, -INFINITY};
#pragma unroll
        for (int nt = 0; nt < 8; ++nt) {
            mx[0] = fmaxf(mx[0], fmaxf(s[nt][0], s[nt][1]));
            mx[1] = fmaxf(mx[1], fmaxf(s[nt][2], s[nt][3]));
        }
#pragma unroll
        for (int r = 0; r < 2; ++r) {
            mx[r] = fmaxf(mx[r], __shfl_xor_sync(0xffffffffu, mx[r], 1));
            mx[r] = fmaxf(mx[r], __shfl_xor_sync(0xffffffffu, mx[r], 2));
        }
        float mn[2], al[2], rs[2];
#pragma unroll
        for (int r = 0; r < 2; ++r) {
            mn[r] = fmaxf(m_[r], mx[r]);
            al[r] = __expf(m_[r] - mn[r]);
            m_[r] = mn[r];
            rs[r] = 0.f;
        }
#pragma unroll
        for (int nt = 0; nt < 8; ++nt) {
#pragma unroll
            for (int j = 0; j < 4; ++j) {
                int r = j >> 1;
                float p = __expf(s[nt][j] - mn[r]);
                s[nt][j] = p;
                rs[r] += p;
            }
        }
#pragma unroll
        for (int r = 0; r < 2; ++r) {
            rs[r] += __shfl_xor_sync(0xffffffffu, rs[r], 1);
            rs[r] += __shfl_xor_sync(0xffffffffu, rs[r], 2);
            l_[r] = l_[r] * al[r] + rs[r];
        }
#pragma unroll
        for (int nt = 0; nt < 8; ++nt) {
            o[nt][0] *= al[0]; o[nt][1] *= al[0];
            o[nt][2] *= al[1]; o[nt][3] *= al[1];
        }

        // O += P V (1 pass)
#pragma unroll
        for (int ks = 0; ks < 4; ++ks) {
            const int ta = 2 * ks, tb = 2 * ks + 1;
            uint32_t pa[4];
            {
                __half2 p0 = __floats2half2_rn(s[ta][0], s[ta][1]);
                __half2 p1 = __floats2half2_rn(s[ta][2], s[ta][3]);
                __half2 p2 = __floats2half2_rn(s[tb][0], s[tb][1]);
                __half2 p3 = __floats2half2_rn(s[tb][2], s[tb][3]);
                pa[0] = *(uint32_t*)&p0; pa[1] = *(uint32_t*)&p1;
                pa[2] = *(uint32_t*)&p2; pa[3] = *(uint32_t*)&p3;
            }
            uint32_t vf_[8][2];
#pragma unroll
            for (int np = 0; np < 4; ++np) {
                uint32_t off = (uint32_t)(ks * 16 * 144) + np * 32;
                LDSM_X4_T(vf_[2 * np][0], vf_[2 * np][1], vf_[2 * np + 1][0], vf_[2 * np + 1][1], vbase + off);
            }
#pragma unroll
            for (int nt = 0; nt < 8; ++nt)
                MMA16816F(o[nt], pa, vf_[nt]);
        }
        __syncthreads();
    }

    // epilogue: Y = O / l, fp16 hi/lo, layout [B,T,C]
    const int bb = bh >> 4;
    const int hh = bh & 15;
#pragma unroll
    for (int r = 0; r < 2; ++r) {
        int t = q0 + w * 16 + (l >> 2) + r * 8;
        float inv = 1.f / l_[r];
        size_t rowbase = (size_t)(bb * 2048 + t) * 1024 + hh * 64 + ((l & 3) << 1);
#pragma unroll
        for (int nt = 0; nt < 8; ++nt) {
            uint32_t hp, lp;
            splitH2(o[nt][2 * r] * inv, o[nt][2 * r + 1] * inv, hp, lp);
            *(uint32_t*)&g_Yh[rowbase + nt * 8] = hp;
            *(uint32_t*)&g_Yl[rowbase + nt * 8] = lp;
        }
    }
}

// ---------------------------------------------------------------------------
extern "C" void kernel_launch(void* const* d_in, const int* in_sizes, int n_in,
                              void* d_out, int out_size)
{
    (void)in_sizes; (void)n_in; (void)out_size;
    const float* x = (const float*)d_in[0];
    const float* wq = (const float*)d_in[1];
    const float* wp = (const float*)d_in[2];
    float* out = (float*)d_out;

    cudaFuncSetAttribute(gemm_hmma_kernel, cudaFuncAttributeMaxDynamicSharedMemorySize, GSM_TOTAL);
    cudaFuncSetAttribute(flash_hmma_kernel, cudaFuncAttributeMaxDynamicSharedMemorySize, FLASH_SMEM);

    __half *xh, *xl, *wqf, *wpf, *yh, *yl;
    cudaGetSymbolAddress((void**)&xh, g_Xh);
    cudaGetSymbolAddress((void**)&xl, g_Xl);
    cudaGetSymbolAddress((void**)&wqf, g_Wqf);
    cudaGetSymbolAddress((void**)&wpf, g_Wpf);
    cudaGetSymbolAddress((void**)&yh, g_Yh);
    cudaGetSymbolAddress((void**)&yl, g_Yl);

    split16_kernel<<<8192, 256>>>(x, xh, xl, 2097152);
    conv16_kernel<<<3072, 256>>>(wq, wqf, 786432);
    conv16_kernel<<<1024, 256>>>(wp, wpf, 262144);

    gemm_hmma_kernel<<<dim3(24, 64), 256, GSM_TOTAL>>>(xh, xl, wqf, nullptr, 0);
    flash_hmma_kernel<<<dim3(16, 64), 256, FLASH_SMEM>>>();
    gemm_hmma_kernel<<<dim3(8, 64), 256, GSM_TOTAL>>>(yh, yl, wpf, out, 1);
}

// round 8
// speedup vs baseline: 9.2427x; 1.3548x over previous
#include <cuda_runtime.h>
#include <cuda_fp16.h>
#include <cstdint>
#include <math.h>

// Problem: x[4,2048,1024], W_qkv[3072,1024], W_proj[1024,1024] -> out[4,2048,1024]
#define KDIM 1024

// ---------------- device scratch (allocation-free) ----------------
__device__ __half g_Xf[8388608];
__device__ __half g_Wqf[3145728];
__device__ __half g_Wpf[1048576];
__device__ __half g_Qf[8388608];    // pre-scaled by 0.125
__device__ __half g_Kf[8388608];
__device__ __half g_Vf[8388608];
__device__ __half g_Yf[8388608];

__device__ __forceinline__ uint32_t smem_u32(const void* p) {
    uint32_t a;
    asm("{ .reg .u64 t; cvta.to.shared.u64 t, %1; cvt.u32.u64 %0, t; }" : "=r"(a) : "l"(p));
    return a;
}

#define LDSM_X4(r0, r1, r2, r3, addr) \
    asm volatile("ldmatrix.sync.aligned.m8n8.x4.shared.b16 {%0,%1,%2,%3}, [%4];" \
                 : "=r"(r0), "=r"(r1), "=r"(r2), "=r"(r3) : "r"(addr))

#define LDSM_X4_T(r0, r1, r2, r3, addr) \
    asm volatile("ldmatrix.sync.aligned.m8n8.x4.trans.shared.b16 {%0,%1,%2,%3}, [%4];" \
                 : "=r"(r0), "=r"(r1), "=r"(r2), "=r"(r3) : "r"(addr))

#define MMA16816F(c, a, b) \
    asm volatile("mma.sync.aligned.m16n8k16.row.col.f32.f16.f16.f32 " \
                 "{%0,%1,%2,%3}, {%4,%5,%6,%7}, {%8,%9}, {%0,%1,%2,%3};" \
                 : "+f"((c)[0]), "+f"((c)[1]), "+f"((c)[2]), "+f"((c)[3]) \
                 : "r"((a)[0]), "r"((a)[1]), "r"((a)[2]), "r"((a)[3]), \
                   "r"((b)[0]), "r"((b)[1]))

#define CP_ASYNC16(dst, src) \
    asm volatile("cp.async.cg.shared.global [%0], [%1], 16;" :: "r"(dst), "l"(src) : "memory")
#define CP_COMMIT() asm volatile("cp.async.commit_group;" ::: "memory")
#define CP_WAIT1()  asm volatile("cp.async.wait_group 1;" ::: "memory")
#define CP_WAIT0()  asm volatile("cp.async.wait_group 0;" ::: "memory")

// ---------------------------------------------------------------------------
// conv16: fp32 -> fp16
// ---------------------------------------------------------------------------
__global__ __launch_bounds__(256) void conv16_kernel(const float* __restrict__ src,
                                                     __half* __restrict__ dst, int n4)
{
    int i = blockIdx.x * blockDim.x + threadIdx.x;
    if (i >= n4) return;
    float4 v = ((const float4*)src)[i];
    __half2 a = __floats2half2_rn(v.x, v.y);
    __half2 b = __floats2half2_rn(v.z, v.w);
    ((uint2*)dst)[i] = make_uint2(*(uint32_t*)&a, *(uint32_t*)&b);
}

// ---------------------------------------------------------------------------
// HMMA fp16 single-pass GEMM: C = A * B^T, fp32 accumulate.
// CTA 128x128, 8 warps (2M x 4N), K_tile=64, 16 iters, 2-stage cp.async.
// mode 0: QKV -> Qf(x0.125), Kf, Vf
// mode 1: row-major fp32 Out
// ---------------------------------------------------------------------------
#define GTILE  (128 * 144)           // 18432 B
#define GSTAGE (2 * GTILE)           // 36864 B: A, B
#define GSM_TOTAL (2 * GSTAGE)       // 73728 B

__global__ __launch_bounds__(256, 2)
void gemm_hmma_kernel(const __half* __restrict__ A,
                      const __half* __restrict__ B,
                      float* __restrict__ Out, int mode)
{
    extern __shared__ char smem[];
    const int tid = threadIdx.x;
    const int wid = tid >> 5;
    const int l = tid & 31;
    const int m0 = blockIdx.y << 7;
    const int n0 = blockIdx.x << 7;
    const int warpM = wid >> 2;
    const int warpN = wid & 3;

    float acc[4][4][4];
#pragma unroll
    for (int i = 0; i < 4; ++i)
#pragma unroll
        for (int j = 0; j < 4; ++j)
#pragma unroll
            for (int k = 0; k < 4; ++k) acc[i][j][k] = 0.f;

    const int aRow = warpM * 64 + (l & 15);
    const uint32_t aOff = (uint32_t)(aRow * 144 + (((l >> 4) << 3) << 1));
    const int bRow = warpN * 32 + (l & 7) + ((l >> 4) << 3);
    const uint32_t bOff = (uint32_t)(bRow * 144 + ((((l >> 3) & 1) << 3) << 1));
    const uint32_t smb = smem_u32(smem);

    // stage issue: 2048 16B chunks, 8 per thread
    auto issue = [&](int stg, int k0) {
        char* st = smem + stg * GSTAGE;
#pragma unroll
        for (int t = 0; t < 8; ++t) {
            int ci = tid + (t << 8);         // 0..2047
            int mat = ci >> 10;              // 0 A, 1 B
            int pos = ci & 1023;
            int row = pos >> 3;
            int q = pos & 7;
            const __half* src = mat ? B : A;
            int grow = (mat ? n0 : m0) + row;
            uint32_t dst = smem_u32(st + mat * GTILE + row * 144 + (q << 4));
            CP_ASYNC16(dst, src + (size_t)grow * KDIM + k0 + (q << 3));
        }
        CP_COMMIT();
    };

    issue(0, 0);
    for (int iter = 0; iter < 16; ++iter) {
        if (iter < 15) {
            issue((iter + 1) & 1, (iter + 1) << 6);
            CP_WAIT1();
        } else {
            CP_WAIT0();
        }
        __syncthreads();

        const uint32_t sb = smb + (iter & 1) * GSTAGE;
        const uint32_t sA_u = sb + aOff;
        const uint32_t sB_u = sb + GTILE + bOff;

#pragma unroll
        for (int ks = 0; ks < 4; ++ks) {
            const uint32_t kb = (uint32_t)(ks << 5);
            uint32_t bf[4][2];
#pragma unroll
            for (int np = 0; np < 2; ++np) {
                uint32_t o = kb + (uint32_t)(np * 16 * 144);
                LDSM_X4(bf[2 * np][0], bf[2 * np][1], bf[2 * np + 1][0], bf[2 * np + 1][1], sB_u + o);
            }
            uint32_t af[4][4];
#pragma unroll
            for (int mt = 0; mt < 4; ++mt) {
                uint32_t o = kb + (uint32_t)(mt * 16 * 144);
                LDSM_X4(af[mt][0], af[mt][1], af[mt][2], af[mt][3], sA_u + o);
            }
#pragma unroll
            for (int mt = 0; mt < 4; ++mt)
#pragma unroll
                for (int nt = 0; nt < 4; ++nt)
                    MMA16816F(acc[mt][nt], af[mt], bf[nt]);
        }
        __syncthreads();
    }

    // epilogue
#pragma unroll
    for (int mt = 0; mt < 4; ++mt) {
#pragma unroll
        for (int nt = 0; nt < 4; ++nt) {
            int r0 = m0 + warpM * 64 + mt * 16 + (l >> 2);
            int col = n0 + warpN * 32 + nt * 8 + ((l & 3) << 1);
#pragma unroll
            for (int half = 0; half < 2; ++half) {
                int m = r0 + half * 8;
                float vx = acc[mt][nt][half * 2], vy = acc[mt][nt][half * 2 + 1];
                if (mode == 0) {
                    int which = col >> 10;
                    int c = col & 1023;
                    int h = c >> 6;
                    int d = c & 63;
                    int bb = m >> 11;
                    int t = m & 2047;
                    size_t idx = (size_t)(((bb << 4) | h) * 2048 + t) * 64 + d;
                    if (which == 0) {
                        __half2 q2 = __floats2half2_rn(vx * 0.125f, vy * 0.125f);
                        *(__half2*)&g_Qf[idx] = q2;
                    } else if (which == 1) {
                        *(__half2*)&g_Kf[idx] = __floats2half2_rn(vx, vy);
                    } else {
                        *(__half2*)&g_Vf[idx] = __floats2half2_rn(vx, vy);
                    }
                } else {
                    *(float2*)&Out[(size_t)m * 1024 + col] = make_float2(vx, vy);
                }
            }
        }
    }
}

// ---------------------------------------------------------------------------
// Flash attention, fp16 HMMA: S = (Q/8)K 1 pass; O += P V 1 pass.
// CTA: one (b,h) x 128 rows, 8 warps x 16 rows. Bc=64, double-buffered cp.async.
// smem: Qf [0,18432); stage s at 18432 + s*18432: K[0,9216) V[9216,18432)
// ---------------------------------------------------------------------------
#define FQ_SZ 18432
#define FSTAGE 18432
#define FLASH_SMEM (FQ_SZ + 2 * FSTAGE)   // 55296

__device__ __forceinline__ void kv_issue(int tid, char* sb, int k0,
                                         const __half* Kf, const __half* Vf)
{
#pragma unroll
    for (int t = 0; t < 4; ++t) {
        int ci = tid + (t << 8);          // 0..1023
        int mat = ci >> 9;                // 0 K, 1 V
        int r = (ci & 511) >> 3;
        int q = ci & 7;
        const __half* src = mat ? Vf : Kf;
        uint32_t dst = smem_u32(sb + mat * 9216 + r * 144 + (q << 4));
        CP_ASYNC16(dst, src + (size_t)(k0 + r) * 64 + (q << 3));
    }
    CP_COMMIT();
}

__global__ __launch_bounds__(256, 2) void flash_hmma_kernel()
{
    extern __shared__ char sm[];
    const int tid = threadIdx.x;
    const int w = tid >> 5;
    const int l = tid & 31;
    const int bh = blockIdx.y;
    const int q0 = blockIdx.x << 7;

    const size_t hb = (size_t)bh * 2048 * 64;
    const __half* Qp = g_Qf + hb;
    const __half* Kp = g_Kf + hb;
    const __half* Vp = g_Vf + hb;

    // Q tile -> smem
#pragma unroll
    for (int t = 0; t < 4; ++t) {
        int ci = tid + (t << 8);
        int r = ci >> 3;
        int q = ci & 7;
        *(uint4*)(sm + r * 144 + (q << 4)) = *(const uint4*)(Qp + (size_t)(q0 + r) * 64 + (q << 3));
    }
    kv_issue(tid, sm + FQ_SZ, 0, Kp, Vp);
    __syncthreads();

    uint32_t qf[4][4];
    {
        uint32_t qb = smem_u32(sm) + (uint32_t)((w * 16 + (l & 15)) * 144 + (((l >> 4) << 3) << 1));
#pragma unroll
        for (int ks = 0; ks < 4; ++ks)
            LDSM_X4(qf[ks][0], qf[ks][1], qf[ks][2], qf[ks][3], qb + ks * 32);
    }

    float o[8][4];
#pragma unroll
    for (int nt = 0; nt < 8; ++nt)
#pragma unroll
        for (int j = 0; j < 4; ++j) o[nt][j] = 0.f;
    float m_[2] = {-INFINITY, -INFINITY};
    float l_[2] = {0.f, 0.f};

    const uint32_t kb_off = (uint32_t)((((l & 7) + ((l >> 4) << 3)) * 144) + ((((l >> 3) & 1) << 3) << 1));
    const uint32_t vb_off = (uint32_t)((((l & 7) + (((l >> 3) & 1) << 3)) * 144) + (((l >> 4) << 3) << 1));

    for (int jb = 0; jb < 32; ++jb) {
        if (jb + 1 < 32) {
            kv_issue(tid, sm + FQ_SZ + ((jb + 1) & 1) * FSTAGE, (jb + 1) << 6, Kp, Vp);
            CP_WAIT1();
        } else {
            CP_WAIT0();
        }
        __syncthreads();

        char* sb = sm + FQ_SZ + (jb & 1) * FSTAGE;
        const uint32_t kbase = smem_u32(sb) + kb_off;
        const uint32_t vbase = smem_u32(sb) + 9216 + vb_off;

        // S = Q K^T (1 pass; Q pre-scaled)
        float s[8][4];
#pragma unroll
        for (int nt = 0; nt < 8; ++nt)
#pragma unroll
            for (int j = 0; j < 4; ++j) s[nt][j] = 0.f;

#pragma unroll
        for (int ks = 0; ks < 4; ++ks) {
            uint32_t kh_[8][2];
#pragma unroll
            for (int np = 0; np < 4; ++np) {
                uint32_t off = (uint32_t)(np * 16 * 144) + ks * 32;
                LDSM_X4(kh_[2 * np][0], kh_[2 * np][1], kh_[2 * np + 1][0], kh_[2 * np + 1][1], kbase + off);
            }
#pragma unroll
            for (int nt = 0; nt < 8; ++nt)
                MMA16816F(s[nt], qf[ks], kh_[nt]);
        }

        // online softmax
        float mx[2] = {-INFINITY, -INFINITY};
#pragma unroll
        for (int nt = 0; nt < 8; ++nt) {
            mx[0] = fmaxf(mx[0], fmaxf(s[nt][0], s[nt][1]));
            mx[1] = fmaxf(mx[1], fmaxf(s[nt][2], s[nt][3]));
        }
#pragma unroll
        for (int r = 0; r < 2; ++r) {
            mx[r] = fmaxf(mx[r], __shfl_xor_sync(0xffffffffu, mx[r], 1));
            mx[r] = fmaxf(mx[r], __shfl_xor_sync(0xffffffffu, mx[r], 2));
        }
        float mn[2], al[2], rs[2];
#pragma unroll
        for (int r = 0; r < 2; ++r) {
            mn[r] = fmaxf(m_[r], mx[r]);
            al[r] = __expf(m_[r] - mn[r]);
            m_[r] = mn[r];
            rs[r] = 0.f;
        }
#pragma unroll
        for (int nt = 0; nt < 8; ++nt) {
#pragma unroll
            for (int j = 0; j < 4; ++j) {
                int r = j >> 1;
                float p = __expf(s[nt][j] - mn[r]);
                s[nt][j] = p;
                rs[r] += p;
            }
        }
#pragma unroll
        for (int r = 0; r < 2; ++r) {
            rs[r] += __shfl_xor_sync(0xffffffffu, rs[r], 1);
            rs[r] += __shfl_xor_sync(0xffffffffu, rs[r], 2);
            l_[r] = l_[r] * al[r] + rs[r];
        }
#pragma unroll
        for (int nt = 0; nt < 8; ++nt) {
            o[nt][0] *= al[0]; o[nt][1] *= al[0];
            o[nt][2] *= al[1]; o[nt][3] *= al[1];
        }

        // O += P V (1 pass)
#pragma unroll
        for (int ks = 0; ks < 4; ++ks) {
            const int ta = 2 * ks, tb = 2 * ks + 1;
            uint32_t pa[4];
            {
                __half2 p0 = __floats2half2_rn(s[ta][0], s[ta][1]);
                __half2 p1 = __floats2half2_rn(s[ta][2], s[ta][3]);
                __half2 p2 = __floats2half2_rn(s[tb][0], s[tb][1]);
                __half2 p3 = __floats2half2_rn(s[tb][2], s[tb][3]);
                pa[0] = *(uint32_t*)&p0; pa[1] = *(uint32_t*)&p1;
                pa[2] = *(uint32_t*)&p2; pa[3] = *(uint32_t*)&p3;
            }
            uint32_t vf_[8][2];
#pragma unroll
            for (int np = 0; np < 4; ++np) {
                uint32_t off = (uint32_t)(ks * 16 * 144) + np * 32;
                LDSM_X4_T(vf_[2 * np][0], vf_[2 * np][1], vf_[2 * np + 1][0], vf_[2 * np + 1][1], vbase + off);
            }
#pragma unroll
            for (int nt = 0; nt < 8; ++nt)
                MMA16816F(o[nt], pa, vf_[nt]);
        }
        __syncthreads();
    }

    // epilogue: Y = O / l, fp16, layout [B,T,C]
    const int bb = bh >> 4;
    const int hh = bh & 15;
#pragma unroll
    for (int r = 0; r < 2; ++r) {
        int t = q0 + w * 16 + (l >> 2) + r * 8;
        float inv = 1.f / l_[r];
        size_t rowbase = (size_t)(bb * 2048 + t) * 1024 + hh * 64 + ((l & 3) << 1);
#pragma unroll
        for (int nt = 0; nt < 8; ++nt) {
            __half2 y2 = __floats2half2_rn(o[nt][2 * r] * inv, o[nt][2 * r + 1] * inv);
            *(__half2*)&g_Yf[rowbase + nt * 8] = y2;
        }
    }
}

// ---------------------------------------------------------------------------
extern "C" void kernel_launch(void* const* d_in, const int* in_sizes, int n_in,
                              void* d_out, int out_size)
{
    (void)in_sizes; (void)n_in; (void)out_size;
    const float* x = (const float*)d_in[0];
    const float* wq = (const float*)d_in[1];
    const float* wp = (const float*)d_in[2];
    float* out = (float*)d_out;

    cudaFuncSetAttribute(gemm_hmma_kernel, cudaFuncAttributeMaxDynamicSharedMemorySize, GSM_TOTAL);
    cudaFuncSetAttribute(flash_hmma_kernel, cudaFuncAttributeMaxDynamicSharedMemorySize, FLASH_SMEM);

    __half *xf, *wqf, *wpf, *yf;
    cudaGetSymbolAddress((void**)&xf, g_Xf);
    cudaGetSymbolAddress((void**)&wqf, g_Wqf);
    cudaGetSymbolAddress((void**)&wpf, g_Wpf);
    cudaGetSymbolAddress((void**)&yf, g_Yf);

    conv16_kernel<<<8192, 256>>>(x, xf, 2097152);
    conv16_kernel<<<3072, 256>>>(wq, wqf, 786432);
    conv16_kernel<<<1024, 256>>>(wp, wpf, 262144);

    gemm_hmma_kernel<<<dim3(24, 64), 256, GSM_TOTAL>>>(xf, wqf, nullptr, 0);
    flash_hmma_kernel<<<dim3(16, 64), 256, FLASH_SMEM>>>();
    gemm_hmma_kernel<<<dim3(8, 64), 256, GSM_TOTAL>>>(yf, wpf, out, 1);
}